// round 7
// baseline (speedup 1.0000x reference)
#include <cuda_runtime.h>
#include <cuda_bf16.h>
#include <cstdint>
#include <math.h>

#define S_TOK 2048
#define EMB   1152
#define NH    16
#define HD    72
#define KDIM  1152
#define BK    32
#define NCHUNK (KDIM / BK)          // 36

// ---- GEMM (BM=128, BN=64, 3-stage) smem layout ----
#define G_AH 0
#define G_AL 10240
#define G_BH 20480
#define G_BL 25600
#define G_STAGE 30720
#define GEMM_SMEM (3 * G_STAGE)     // 92160

// ---- attention smem layout: Q persistent + 3 KV stages of 32 keys ----
#define A_ROWB 176
#define AQ_H 0
#define AQ_L 22528
#define AKV0 45056
#define KVS  22528
#define KO_H 0
#define KO_L 5632
#define VO_H 11264
#define VO_L 16896
#define ATTN_SMEM 112640

// ---------------- scratch ----------------------------------------------------
__device__ float g_q[S_TOK * EMB];
__device__ float g_k[S_TOK * EMB];

__device__ __align__(16) __nv_bfloat16 g_hs_hi[S_TOK * EMB];   // hs hi, then Q-prep hi
__device__ __align__(16) __nv_bfloat16 g_hs_lo[S_TOK * EMB];
__device__ __align__(16) __nv_bfloat16 g_k_hi[S_TOK * EMB];
__device__ __align__(16) __nv_bfloat16 g_k_lo[S_TOK * EMB];
__device__ __align__(16) __nv_bfloat16 g_v_hi[S_TOK * EMB];
__device__ __align__(16) __nv_bfloat16 g_v_lo[S_TOK * EMB];
__device__ __align__(16) __nv_bfloat16 g_a_hi[S_TOK * EMB];
__device__ __align__(16) __nv_bfloat16 g_a_lo[S_TOK * EMB];
__device__ __align__(16) __nv_bfloat16 g_w_hi[4][EMB * EMB];
__device__ __align__(16) __nv_bfloat16 g_w_lo[4][EMB * EMB];

// ---------------- helpers ----------------------------------------------------
__device__ __forceinline__ uint32_t smem_u32(const void* p) {
    uint32_t a;
    asm("{ .reg .u64 t; cvta.to.shared.u64 t, %1; cvt.u32.u64 %0, t; }"
        : "=r"(a) : "l"(p));
    return a;
}

#define CP_ASYNC16(dst, src) \
    asm volatile("cp.async.cg.shared.global [%0], [%1], 16;" :: "r"(dst), "l"(src))
#define CP_COMMIT() asm volatile("cp.async.commit_group;" ::: "memory")
#define CP_WAIT(n)  asm volatile("cp.async.wait_group %0;" :: "n"(n) : "memory")

#define LDSM_X4(r, addr) \
    asm volatile("ldmatrix.sync.aligned.m8n8.x4.shared.b16 {%0,%1,%2,%3}, [%4];" \
        : "=r"((r)[0]), "=r"((r)[1]), "=r"((r)[2]), "=r"((r)[3]) : "r"(addr))
#define LDSM_X4_T(r, addr) \
    asm volatile("ldmatrix.sync.aligned.m8n8.x4.trans.shared.b16 {%0,%1,%2,%3}, [%4];" \
        : "=r"((r)[0]), "=r"((r)[1]), "=r"((r)[2]), "=r"((r)[3]) : "r"(addr))

#define MMA16816(d, a, b0, b1) \
    asm volatile("mma.sync.aligned.m16n8k16.row.col.f32.bf16.bf16.f32 " \
        "{%0,%1,%2,%3}, {%4,%5,%6,%7}, {%8,%9}, {%0,%1,%2,%3};" \
        : "+f"((d)[0]), "+f"((d)[1]), "+f"((d)[2]), "+f"((d)[3]) \
        : "r"((a)[0]), "r"((a)[1]), "r"((a)[2]), "r"((a)[3]), "r"(b0), "r"(b1))

__device__ __forceinline__ uint32_t pk2(float lo, float hi) {
    uint32_t r;
    asm("cvt.rn.bf16x2.f32 %0, %1, %2;" : "=r"(r) : "f"(hi), "f"(lo));
    return r;
}
__device__ __forceinline__ float f2b(float x) {
    return __bfloat162float(__float2bfloat16(x));
}

// ---------------------------------------------------------------------------
// split-bf16 HMMA GEMM, BM=128, BN=64, 3-stage cp.async, 256 thr, occ 2.
// splitOut=0: C fp32 (+bias). splitOut=1: bf16 hi/lo out (+bias).
// ---------------------------------------------------------------------------
__device__ __forceinline__ void gemm_mma_tile64(
    const __nv_bfloat16* __restrict__ Ahi, const __nv_bfloat16* __restrict__ Alo,
    const __nv_bfloat16* __restrict__ Whi, const __nv_bfloat16* __restrict__ Wlo,
    const float* __restrict__ bias, float* __restrict__ C,
    __nv_bfloat16* __restrict__ Chi, __nv_bfloat16* __restrict__ Clo,
    int splitOut)
{
    extern __shared__ __align__(16) char smem[];
    const uint32_t sbase = smem_u32(smem);

    const int tid  = threadIdx.x;
    const int lane = tid & 31;
    const int w    = tid >> 5;
    const int wm   = w & 3;              // 4 m-blocks of 32
    const int wn   = w >> 2;             // 2 n-blocks of 32
    const int rBase = blockIdx.y * 128;
    const int cBase = blockIdx.x * 64;

    const int j  = lane >> 3;
    const int l8 = lane & 7;
    const uint32_t a_lane_off =
        (uint32_t)((wm * 32 + (j & 1) * 8 + l8) * 80 + (j >> 1) * 16);
    const uint32_t b_lane_off =
        (uint32_t)((wn * 32 + (j >> 1) * 8 + l8) * 80 + (j & 1) * 16);

    float acc[2][4][4];
#pragma unroll
    for (int mt = 0; mt < 2; mt++)
#pragma unroll
        for (int nt = 0; nt < 4; nt++)
#pragma unroll
            for (int e = 0; e < 4; e++) acc[mt][nt][e] = 0.f;

    auto load_stage = [&](int s, int kc) {
        const uint32_t dst0 = sbase + s * G_STAGE;
        {   // A: 128 rows x 64B
            const int r = tid >> 1, c0 = (tid & 1) * 2;
            const size_t g = (size_t)(rBase + r) * KDIM + kc + c0 * 8;
            const uint32_t d = dst0 + G_AH + r * 80 + c0 * 16;
            CP_ASYNC16(d,      Ahi + g);
            CP_ASYNC16(d + 16, Ahi + g + 8);
            const uint32_t dl = dst0 + G_AL + r * 80 + c0 * 16;
            CP_ASYNC16(dl,      Alo + g);
            CP_ASYNC16(dl + 16, Alo + g + 8);
        }
        {   // B: 64 rows x 64B
            const int r = tid >> 2, c = tid & 3;
            const size_t g = (size_t)(cBase + r) * KDIM + kc + c * 8;
            CP_ASYNC16(dst0 + G_BH + r * 80 + c * 16, Whi + g);
            CP_ASYNC16(dst0 + G_BL + r * 80 + c * 16, Wlo + g);
        }
    };

    load_stage(0, 0); CP_COMMIT();
    load_stage(1, BK); CP_COMMIT();

    for (int i = 0; i < NCHUNK; i++) {
        if (i + 1 < NCHUNK) { CP_WAIT(1); } else { CP_WAIT(0); }
        __syncthreads();
        if (i + 2 < NCHUNK) {
            load_stage((i + 2) % 3, (i + 2) * BK);
            CP_COMMIT();
        }

        const uint32_t base = sbase + (i % 3) * G_STAGE;
#pragma unroll
        for (int ks = 0; ks < 2; ks++) {
            const uint32_t koff = ks * 32;
            uint32_t bh[2][4], bl[2][4];
#pragma unroll
            for (int p = 0; p < 2; p++) {
                const uint32_t bo = base + G_BH + b_lane_off + p * 1280 + koff;
                LDSM_X4(bh[p], bo);
                LDSM_X4(bl[p], bo + (G_BL - G_BH));
            }
#pragma unroll
            for (int mt = 0; mt < 2; mt++) {
                uint32_t ah[4], al[4];
                const uint32_t ao = base + G_AH + a_lane_off + mt * 1280 + koff;
                LDSM_X4(ah, ao);
                LDSM_X4(al, ao + (G_AL - G_AH));
#pragma unroll
                for (int nt = 0; nt < 4; nt++) {
                    const int p = nt >> 1, s2 = (nt & 1) * 2;
                    MMA16816(acc[mt][nt], ah, bh[p][s2], bh[p][s2 + 1]);
                    MMA16816(acc[mt][nt], al, bh[p][s2], bh[p][s2 + 1]);
                    MMA16816(acc[mt][nt], ah, bl[p][s2], bl[p][s2 + 1]);
                }
            }
        }
    }

    const int qr = lane >> 2;
    const int qc = (lane & 3) * 2;
#pragma unroll
    for (int mt = 0; mt < 2; mt++) {
#pragma unroll
        for (int nt = 0; nt < 4; nt++) {
            const int row = rBase + wm * 32 + mt * 16 + qr;
            const int col = cBase + wn * 32 + nt * 8 + qc;
            const float b0 = bias[col], b1 = bias[col + 1];
            float v00 = acc[mt][nt][0] + b0, v01 = acc[mt][nt][1] + b1;
            float v10 = acc[mt][nt][2] + b0, v11 = acc[mt][nt][3] + b1;
            if (!splitOut) {
                *(float2*)(C + (size_t)row * EMB + col) = make_float2(v00, v01);
                *(float2*)(C + (size_t)(row + 8) * EMB + col) = make_float2(v10, v11);
            } else {
                float h00 = f2b(v00), h01 = f2b(v01), h10 = f2b(v10), h11 = f2b(v11);
                *(uint32_t*)(Chi + (size_t)row * EMB + col) = pk2(v00, v01);
                *(uint32_t*)(Chi + (size_t)(row + 8) * EMB + col) = pk2(v10, v11);
                *(uint32_t*)(Clo + (size_t)row * EMB + col) = pk2(v00 - h00, v01 - h01);
                *(uint32_t*)(Clo + (size_t)(row + 8) * EMB + col) = pk2(v10 - h10, v11 - h11);
            }
        }
    }
}

__global__ __launch_bounds__(256, 2) void qkv_mma_kernel(
    const __nv_bfloat16* __restrict__ Ahi, const __nv_bfloat16* __restrict__ Alo,
    const __nv_bfloat16* __restrict__ whi, const __nv_bfloat16* __restrict__ wlo,
    const float* __restrict__ qb, const float* __restrict__ kb,
    const float* __restrict__ vb,
    float* __restrict__ Cq, float* __restrict__ Ck,
    __nv_bfloat16* __restrict__ Vhi, __nv_bfloat16* __restrict__ Vlo)
{
    const __nv_bfloat16* Bhi = whi + (size_t)blockIdx.z * EMB * EMB;
    const __nv_bfloat16* Blo = wlo + (size_t)blockIdx.z * EMB * EMB;
    if (blockIdx.z == 0)
        gemm_mma_tile64(Ahi, Alo, Bhi, Blo, qb, Cq, nullptr, nullptr, 0);
    else if (blockIdx.z == 1)
        gemm_mma_tile64(Ahi, Alo, Bhi, Blo, kb, Ck, nullptr, nullptr, 0);
    else
        gemm_mma_tile64(Ahi, Alo, Bhi, Blo, vb, nullptr, Vhi, Vlo, 1);
}

__global__ __launch_bounds__(256, 2) void oproj_mma_kernel(
    const __nv_bfloat16* __restrict__ Ahi, const __nv_bfloat16* __restrict__ Alo,
    const __nv_bfloat16* __restrict__ Bhi, const __nv_bfloat16* __restrict__ Blo,
    const float* __restrict__ bias, float* __restrict__ C)
{
    gemm_mma_tile64(Ahi, Alo, Bhi, Blo, bias, C, nullptr, nullptr, 0);
}

// ---------------- batched fp32 -> (bf16 hi, bf16 lo) split ------------------
#define HS8 (S_TOK * EMB / 8)
#define W8  (EMB * EMB / 8)
#define CVT_TOTAL (HS8 + 4 * W8)

__global__ __launch_bounds__(256) void cvt_all_kernel(
    const float* __restrict__ hs, const float* __restrict__ qw,
    const float* __restrict__ kw, const float* __restrict__ vw,
    const float* __restrict__ ow,
    __nv_bfloat16* __restrict__ hshi, __nv_bfloat16* __restrict__ hslo,
    __nv_bfloat16* __restrict__ whi, __nv_bfloat16* __restrict__ wlo)
{
    int t = blockIdx.x * blockDim.x + threadIdx.x;
    if (t >= CVT_TOTAL) return;
    const float* src;
    __nv_bfloat16 *hi, *lo;
    size_t off;
    if (t < HS8) {
        src = hs; hi = hshi; lo = hslo; off = (size_t)t * 8;
    } else {
        int r = t - HS8;
        int wsel = r / W8;
        int loc = r - wsel * W8;
        const float* ws[4] = { qw, kw, vw, ow };
        src = ws[wsel];
        hi = whi + (size_t)wsel * EMB * EMB;
        lo = wlo + (size_t)wsel * EMB * EMB;
        off = (size_t)loc * 8;
    }
    const float4* s4 = (const float4*)(src + off);
    float4 a = s4[0], b = s4[1];
    float v[8] = {a.x, a.y, a.z, a.w, b.x, b.y, b.z, b.w};
    __nv_bfloat16 h[8], l[8];
#pragma unroll
    for (int k = 0; k < 8; k++) {
        h[k] = __float2bfloat16(v[k]);
        l[k] = __float2bfloat16(v[k] - __bfloat162float(h[k]));
    }
    *(uint4*)(hi + off) = *(uint4*)h;
    *(uint4*)(lo + off) = *(uint4*)l;
}

// ---------------- prep: RoPE + (scale) + split Q and K ----------------------
__global__ __launch_bounds__(256) void prep_qk_kernel(
    const float* __restrict__ Q, const float* __restrict__ K,
    __nv_bfloat16* __restrict__ qh, __nv_bfloat16* __restrict__ ql,
    __nv_bfloat16* __restrict__ kh, __nv_bfloat16* __restrict__ kl,
    const float* __restrict__ cosp, const float* __restrict__ sinp)
{
    int idx = blockIdx.x * blockDim.x + threadIdx.x;
    if (idx >= S_TOK * NH * 9) return;
    const int c = idx % 9;
    const int t = idx / 9;
    const int h = t % NH;
    const int s = t / NH;
    const size_t gb = (size_t)s * EMB + h * HD + c * 4;
    const size_t pb = (size_t)s * HD + c * 4;
    const float scale = rsqrtf((float)HD);

    float4 cl = *(const float4*)(cosp + pb);
    float4 sl = *(const float4*)(sinp + pb);
    float4 ch = *(const float4*)(cosp + pb + 36);
    float4 sh = *(const float4*)(sinp + pb + 36);

    {   // Q (scaled)
        float4 a = *(const float4*)(Q + gb);
        float4 b = *(const float4*)(Q + gb + 36);
        float lo4[4] = { (a.x * cl.x - b.x * sl.x) * scale, (a.y * cl.y - b.y * sl.y) * scale,
                         (a.z * cl.z - b.z * sl.z) * scale, (a.w * cl.w - b.w * sl.w) * scale };
        float hi4[4] = { (b.x * ch.x + a.x * sh.x) * scale, (b.y * ch.y + a.y * sh.y) * scale,
                         (b.z * ch.z + a.z * sh.z) * scale, (b.w * ch.w + a.w * sh.w) * scale };
        float lr[4], hr[4];
#pragma unroll
        for (int e = 0; e < 4; e++) { lr[e] = lo4[e] - f2b(lo4[e]); hr[e] = hi4[e] - f2b(hi4[e]); }
        *(uint2*)(qh + gb)      = make_uint2(pk2(lo4[0], lo4[1]), pk2(lo4[2], lo4[3]));
        *(uint2*)(qh + gb + 36) = make_uint2(pk2(hi4[0], hi4[1]), pk2(hi4[2], hi4[3]));
        *(uint2*)(ql + gb)      = make_uint2(pk2(lr[0], lr[1]), pk2(lr[2], lr[3]));
        *(uint2*)(ql + gb + 36) = make_uint2(pk2(hr[0], hr[1]), pk2(hr[2], hr[3]));
    }
    {   // K (unscaled)
        float4 a = *(const float4*)(K + gb);
        float4 b = *(const float4*)(K + gb + 36);
        float lo4[4] = { a.x * cl.x - b.x * sl.x, a.y * cl.y - b.y * sl.y,
                         a.z * cl.z - b.z * sl.z, a.w * cl.w - b.w * sl.w };
        float hi4[4] = { b.x * ch.x + a.x * sh.x, b.y * ch.y + a.y * sh.y,
                         b.z * ch.z + a.z * sh.z, b.w * ch.w + a.w * sh.w };
        float lr[4], hr[4];
#pragma unroll
        for (int e = 0; e < 4; e++) { lr[e] = lo4[e] - f2b(lo4[e]); hr[e] = hi4[e] - f2b(hi4[e]); }
        *(uint2*)(kh + gb)      = make_uint2(pk2(lo4[0], lo4[1]), pk2(lo4[2], lo4[3]));
        *(uint2*)(kh + gb + 36) = make_uint2(pk2(hi4[0], hi4[1]), pk2(hi4[2], hi4[3]));
        *(uint2*)(kl + gb)      = make_uint2(pk2(lr[0], lr[1]), pk2(lr[2], lr[3]));
        *(uint2*)(kl + gb + 36) = make_uint2(pk2(hr[0], hr[1]), pk2(hr[2], hr[3]));
    }
}

// ---------------------------------------------------------------------------
// HMMA flash attention v2: prepped operands, cp.async 3-stage 32-key tiles.
// CTA = (128 queries, 1 head), 8 warps, occ 2.
// ---------------------------------------------------------------------------
__global__ __launch_bounds__(256, 2) void attn_mma_kernel(
    const __nv_bfloat16* __restrict__ QH, const __nv_bfloat16* __restrict__ QL,
    const __nv_bfloat16* __restrict__ KHg, const __nv_bfloat16* __restrict__ KLg,
    const __nv_bfloat16* __restrict__ VHg, const __nv_bfloat16* __restrict__ VLg,
    __nv_bfloat16* __restrict__ Ohi, __nv_bfloat16* __restrict__ Olo,
    const int* __restrict__ cu, int nseg)
{
    extern __shared__ __align__(16) char asmem[];
    const uint32_t sb = smem_u32(asmem);

    const int tid  = threadIdx.x;
    const int lane = tid & 31;
    const int w    = tid >> 5;
    const int h    = blockIdx.y;
    const int q0   = blockIdx.x * 128;

    int segStart = 0, segEnd = S_TOK;
    for (int i = 0; i < nseg; i++) {
        int a = cu[i], b = cu[i + 1];
        if (q0 >= a && q0 < b) { segStart = a; segEnd = b; }
    }
    const int ntiles = (segEnd - segStart + 31) / 32;

    // zero pad bytes (head-dims 72..79) for Q rows AND all 3 KV stage buffers.
    // cp.async never writes bytes 144..159 of any row; ldsm DOES read them.
    // THIS was the R6 NaN: garbage K-pad -> 0*NaN in HMMA.
    for (int i = tid; i < 128; i += 256) {
        *(uint4*)(asmem + AQ_H + i * A_ROWB + 144) = make_uint4(0, 0, 0, 0);
        *(uint4*)(asmem + AQ_L + i * A_ROWB + 144) = make_uint4(0, 0, 0, 0);
    }
    for (int i = tid; i < 3 * 32; i += 256) {
        const int b = i / 32, r = i % 32;
        char* rowp = asmem + AKV0 + b * KVS + r * A_ROWB + 144;
        *(uint4*)(rowp + KO_H) = make_uint4(0, 0, 0, 0);
        *(uint4*)(rowp + KO_L) = make_uint4(0, 0, 0, 0);
        *(uint4*)(rowp + VO_H) = make_uint4(0, 0, 0, 0);
        *(uint4*)(rowp + VO_L) = make_uint4(0, 0, 0, 0);
    }

    // stage Q via cp.async (group 0)
    for (int i = tid; i < 128 * 9; i += 256) {
        const int r = i / 9, c = i % 9;
        const size_t g = (size_t)(q0 + r) * EMB + h * HD + c * 8;
        CP_ASYNC16(sb + AQ_H + r * A_ROWB + c * 16, QH + g);
        CP_ASYNC16(sb + AQ_L + r * A_ROWB + c * 16, QL + g);
    }
    CP_COMMIT();

    auto stage_kv = [&](int tt) {
        const int b = tt % 3;
        const int kt = segStart + tt * 32;
        const uint32_t dst0 = sb + AKV0 + b * KVS;
        for (int i = tid; i < 32 * 9; i += 256) {
            const int r = i / 9, c = i % 9;
            const int key = kt + r;
            if (key < segEnd) {
                const size_t g = (size_t)key * EMB + h * HD + c * 8;
                const uint32_t d = dst0 + r * A_ROWB + c * 16;
                CP_ASYNC16(d + KO_H, KHg + g);
                CP_ASYNC16(d + KO_L, KLg + g);
                CP_ASYNC16(d + VO_H, VHg + g);
                CP_ASYNC16(d + VO_L, VLg + g);
            }
        }
    };

    stage_kv(0); CP_COMMIT();
    if (ntiles > 1) { stage_kv(1); CP_COMMIT(); }

    // ldsm lane offsets
    const int j  = lane >> 3;
    const int l8 = lane & 7;
    const uint32_t q_off  = (uint32_t)((16 * w + (j & 1) * 8 + l8) * A_ROWB + (j >> 1) * 16);
    const uint32_t bs_off = (uint32_t)(((j >> 1) * 8 + l8) * A_ROWB + (j & 1) * 16);
    const uint32_t v_off  = (uint32_t)(((j & 1) * 8 + l8) * A_ROWB + (j >> 1) * 16);

    const int qr = lane >> 2;
    const int lc = lane & 3;

    float acc_o[10][4];
#pragma unroll
    for (int dt = 0; dt < 10; dt++)
#pragma unroll
        for (int e = 0; e < 4; e++) acc_o[dt][e] = 0.f;
    float lsum0 = 0.f, lsum1 = 0.f;

    for (int tt = 0; tt < ntiles; tt++) {
        const int kt = segStart + tt * 32;
        if (tt + 1 < ntiles) { CP_WAIT(1); } else { CP_WAIT(0); }
        __syncthreads();
        if (tt + 2 < ntiles) { stage_kv(tt + 2); CP_COMMIT(); }

        const uint32_t kvb = sb + AKV0 + (tt % 3) * KVS;

        // tail: zero K/V data rows beyond segEnd (cp.async skipped them)
        if (kt + 32 > segEnd) {
            for (int i = tid; i < 32 * 9; i += 256) {
                const int r = i / 9, c = i % 9;
                if (kt + r >= segEnd) {
                    char* dp2 = asmem + (kvb - sb) + r * A_ROWB + c * 16;
                    *(uint4*)(dp2 + KO_H) = make_uint4(0, 0, 0, 0);
                    *(uint4*)(dp2 + KO_L) = make_uint4(0, 0, 0, 0);
                    *(uint4*)(dp2 + VO_H) = make_uint4(0, 0, 0, 0);
                    *(uint4*)(dp2 + VO_L) = make_uint4(0, 0, 0, 0);
                }
            }
            __syncthreads();
        }

        // ---- S = Q K^T (3-term split), 32 keys ----------------------------
        float acc_s[4][4];
#pragma unroll
        for (int nt = 0; nt < 4; nt++)
#pragma unroll
            for (int e = 0; e < 4; e++) acc_s[nt][e] = 0.f;

#pragma unroll
        for (int kc = 0; kc < 5; kc++) {
            uint32_t qh[4], ql[4];
            const uint32_t ao = sb + AQ_H + q_off + kc * 32;
            LDSM_X4(qh, ao);
            LDSM_X4(ql, ao + (AQ_L - AQ_H));
#pragma unroll
            for (int np = 0; np < 2; np++) {
                uint32_t bh[4], bl[4];
                const uint32_t bo = kvb + KO_H + bs_off + np * (16 * A_ROWB) + kc * 32;
                LDSM_X4(bh, bo);
                LDSM_X4(bl, bo + (KO_L - KO_H));
                MMA16816(acc_s[2 * np],     qh, bh[0], bh[1]);
                MMA16816(acc_s[2 * np],     ql, bh[0], bh[1]);
                MMA16816(acc_s[2 * np],     qh, bl[0], bl[1]);
                MMA16816(acc_s[2 * np + 1], qh, bh[2], bh[3]);
                MMA16816(acc_s[2 * np + 1], ql, bh[2], bh[3]);
                MMA16816(acc_s[2 * np + 1], qh, bl[2], bl[3]);
            }
        }

        // ---- softmax (unnormalized) + mask --------------------------------
#pragma unroll
        for (int nt = 0; nt < 4; nt++) {
            const int colb = kt + nt * 8 + lc * 2;
            float p0 = (colb     < segEnd) ? __expf(acc_s[nt][0]) : 0.f;
            float p1 = (colb + 1 < segEnd) ? __expf(acc_s[nt][1]) : 0.f;
            float p2 = (colb     < segEnd) ? __expf(acc_s[nt][2]) : 0.f;
            float p3 = (colb + 1 < segEnd) ? __expf(acc_s[nt][3]) : 0.f;
            lsum0 += p0 + p1;
            lsum1 += p2 + p3;
            acc_s[nt][0] = p0; acc_s[nt][1] = p1;
            acc_s[nt][2] = p2; acc_s[nt][3] = p3;
        }

        // ---- O += P V (3-term split) --------------------------------------
#pragma unroll
        for (int kc = 0; kc < 2; kc++) {
            uint32_t pa_h[4], pa_l[4];
            const float* s0 = acc_s[2 * kc];
            const float* s1 = acc_s[2 * kc + 1];
            float h00 = f2b(s0[0]), h01 = f2b(s0[1]), h02 = f2b(s0[2]), h03 = f2b(s0[3]);
            float h10 = f2b(s1[0]), h11 = f2b(s1[1]), h12 = f2b(s1[2]), h13 = f2b(s1[3]);
            pa_h[0] = pk2(h00, h01); pa_h[1] = pk2(h02, h03);
            pa_h[2] = pk2(h10, h11); pa_h[3] = pk2(h12, h13);
            pa_l[0] = pk2(s0[0] - h00, s0[1] - h01); pa_l[1] = pk2(s0[2] - h02, s0[3] - h03);
            pa_l[2] = pk2(s1[0] - h10, s1[1] - h11); pa_l[3] = pk2(s1[2] - h12, s1[3] - h13);
#pragma unroll
            for (int dp = 0; dp < 5; dp++) {
                uint32_t vh[4], vl[4];
                const uint32_t vo = kvb + VO_H + v_off + kc * (16 * A_ROWB) + dp * 32;
                LDSM_X4_T(vh, vo);
                LDSM_X4_T(vl, vo + (VO_L - VO_H));
                MMA16816(acc_o[2 * dp],     pa_h, vh[0], vh[1]);
                MMA16816(acc_o[2 * dp],     pa_l, vh[0], vh[1]);
                MMA16816(acc_o[2 * dp],     pa_h, vl[0], vl[1]);
                MMA16816(acc_o[2 * dp + 1], pa_h, vh[2], vh[3]);
                MMA16816(acc_o[2 * dp + 1], pa_l, vh[2], vh[3]);
                MMA16816(acc_o[2 * dp + 1], pa_h, vl[2], vl[3]);
            }
        }
    }

    // ---- epilogue ---------------------------------------------------------
    lsum0 += __shfl_xor_sync(0xffffffffu, lsum0, 1);
    lsum0 += __shfl_xor_sync(0xffffffffu, lsum0, 2);
    lsum1 += __shfl_xor_sync(0xffffffffu, lsum1, 1);
    lsum1 += __shfl_xor_sync(0xffffffffu, lsum1, 2);
    const float inv0 = 1.0f / lsum0;
    const float inv1 = 1.0f / lsum1;
    const int row0 = q0 + 16 * w + qr;
    const int row1 = row0 + 8;
#pragma unroll
    for (int dt = 0; dt < 9; dt++) {
        const int d = dt * 8 + lc * 2;
        const size_t o0 = (size_t)row0 * EMB + h * HD + d;
        const size_t o1 = (size_t)row1 * EMB + h * HD + d;
        float v00 = acc_o[dt][0] * inv0, v01 = acc_o[dt][1] * inv0;
        float v10 = acc_o[dt][2] * inv1, v11 = acc_o[dt][3] * inv1;
        float h00 = f2b(v00), h01 = f2b(v01), h10 = f2b(v10), h11 = f2b(v11);
        *(uint32_t*)(Ohi + o0) = pk2(v00, v01);
        *(uint32_t*)(Ohi + o1) = pk2(v10, v11);
        *(uint32_t*)(Olo + o0) = pk2(v00 - h00, v01 - h01);
        *(uint32_t*)(Olo + o1) = pk2(v10 - h10, v11 - h11);
    }
}

// ---------------------------------------------------------------------------
extern "C" void kernel_launch(void* const* d_in, const int* in_sizes, int n_in,
                              void* d_out, int out_size)
{
    const float* hs   = (const float*)d_in[0];
    const float* qw   = (const float*)d_in[1];
    const float* qb   = (const float*)d_in[2];
    const float* kw   = (const float*)d_in[3];
    const float* kb   = (const float*)d_in[4];
    const float* vw   = (const float*)d_in[5];
    const float* vb   = (const float*)d_in[6];
    const float* ow   = (const float*)d_in[7];
    const float* ob   = (const float*)d_in[8];
    const float* cosp = (const float*)d_in[9];
    const float* sinp = (const float*)d_in[10];
    const int*   cu   = (const int*)d_in[11];
    const int nseg = in_sizes[11] - 1;

    float *qp, *kp;
    cudaGetSymbolAddress((void**)&qp, g_q);
    cudaGetSymbolAddress((void**)&kp, g_k);
    __nv_bfloat16 *hshi, *hslo, *khi, *klo, *vhi, *vlo, *ahi, *alo, *whi, *wlo;
    cudaGetSymbolAddress((void**)&hshi, g_hs_hi);
    cudaGetSymbolAddress((void**)&hslo, g_hs_lo);
    cudaGetSymbolAddress((void**)&khi, g_k_hi);
    cudaGetSymbolAddress((void**)&klo, g_k_lo);
    cudaGetSymbolAddress((void**)&vhi, g_v_hi);
    cudaGetSymbolAddress((void**)&vlo, g_v_lo);
    cudaGetSymbolAddress((void**)&ahi, g_a_hi);
    cudaGetSymbolAddress((void**)&alo, g_a_lo);
    cudaGetSymbolAddress((void**)&whi, g_w_hi);
    cudaGetSymbolAddress((void**)&wlo, g_w_lo);

    cudaFuncSetAttribute(qkv_mma_kernel,
                         cudaFuncAttributeMaxDynamicSharedMemorySize, GEMM_SMEM);
    cudaFuncSetAttribute(oproj_mma_kernel,
                         cudaFuncAttributeMaxDynamicSharedMemorySize, GEMM_SMEM);
    cudaFuncSetAttribute(attn_mma_kernel,
                         cudaFuncAttributeMaxDynamicSharedMemorySize, ATTN_SMEM);

    // 0) split fp32 -> bf16 hi/lo (hs + 4 weights)
    cvt_all_kernel<<<(CVT_TOTAL + 255) / 256, 256>>>(
        hs, qw, kw, vw, ow, hshi, hslo, whi, wlo);

    // 1) Q/K/V projections (BN=64, occ 2). V written split directly.
    qkv_mma_kernel<<<dim3(EMB / 64, S_TOK / 128, 3), 256, GEMM_SMEM>>>(
        hshi, hslo, whi, wlo, qb, kb, vb, qp, kp, vhi, vlo);

    // 2) prep: RoPE + scale + split Q/K (reuses hs hi/lo buffers for Q)
    prep_qk_kernel<<<(S_TOK * NH * 9 + 255) / 256, 256>>>(
        qp, kp, hshi, hslo, khi, klo, cosp, sinp);

    // 3) HMMA flash attention (pipelined cp.async staging)
    attn_mma_kernel<<<dim3(S_TOK / 128, NH), 256, ATTN_SMEM>>>(
        hshi, hslo, khi, klo, vhi, vlo, ahi, alo, cu, nseg);

    // 4) O projection -> d_out
    oproj_mma_kernel<<<dim3(EMB / 64, S_TOK / 128), 256, GEMM_SMEM>>>(
        ahi, alo, whi + 3 * (size_t)EMB * EMB, wlo + 3 * (size_t)EMB * EMB,
        ob, (float*)d_out);
}

// round 8
// speedup vs baseline: 1.1387x; 1.1387x over previous
#include <cuda_runtime.h>
#include <cuda_bf16.h>
#include <cstdint>
#include <math.h>

#define S_TOK 2048
#define EMB   1152
#define NH    16
#define HD    72
#define KDIM  1152
#define BK    32
#define NCHUNK (KDIM / BK)          // 36
#define TILE_STRIDE 80              // bytes per smem row: 32 bf16 + 16B pad
#define TILE_BYTES  (128 * TILE_STRIDE)   // 10240
#define STAGE_BYTES (4 * TILE_BYTES)      // 40960 (Ahi,Alo,Whi,Wlo)
#define GEMM_SMEM  (2 * STAGE_BYTES)      // 81920

// ---- attention smem layout: Q persistent + 3 KV stages of 32 keys ----
#define A_ROWB 176
#define AQ_H 0
#define AQ_L 22528
#define AKV0 45056
#define KVS  22528
#define KO_H 0
#define KO_L 5632
#define VO_H 11264
#define VO_L 16896
#define ATTN_SMEM 112640

// ---------------- scratch ----------------------------------------------------
__device__ float g_q[S_TOK * EMB];
__device__ float g_k[S_TOK * EMB];

__device__ __align__(16) __nv_bfloat16 g_hs_hi[S_TOK * EMB];   // hs hi, then Q-prep hi
__device__ __align__(16) __nv_bfloat16 g_hs_lo[S_TOK * EMB];
__device__ __align__(16) __nv_bfloat16 g_k_hi[S_TOK * EMB];
__device__ __align__(16) __nv_bfloat16 g_k_lo[S_TOK * EMB];
__device__ __align__(16) __nv_bfloat16 g_v_hi[S_TOK * EMB];
__device__ __align__(16) __nv_bfloat16 g_v_lo[S_TOK * EMB];
__device__ __align__(16) __nv_bfloat16 g_a_hi[S_TOK * EMB];
__device__ __align__(16) __nv_bfloat16 g_a_lo[S_TOK * EMB];
__device__ __align__(16) __nv_bfloat16 g_w_hi[4][EMB * EMB];
__device__ __align__(16) __nv_bfloat16 g_w_lo[4][EMB * EMB];

// ---------------- helpers ----------------------------------------------------
__device__ __forceinline__ uint32_t smem_u32(const void* p) {
    uint32_t a;
    asm("{ .reg .u64 t; cvta.to.shared.u64 t, %1; cvt.u32.u64 %0, t; }"
        : "=r"(a) : "l"(p));
    return a;
}

#define CP_ASYNC16(dst, src) \
    asm volatile("cp.async.cg.shared.global [%0], [%1], 16;" :: "r"(dst), "l"(src))
#define CP_COMMIT() asm volatile("cp.async.commit_group;" ::: "memory")
#define CP_WAIT(n)  asm volatile("cp.async.wait_group %0;" :: "n"(n) : "memory")

#define LDSM_X4(r, addr) \
    asm volatile("ldmatrix.sync.aligned.m8n8.x4.shared.b16 {%0,%1,%2,%3}, [%4];" \
        : "=r"((r)[0]), "=r"((r)[1]), "=r"((r)[2]), "=r"((r)[3]) : "r"(addr))
#define LDSM_X4_T(r, addr) \
    asm volatile("ldmatrix.sync.aligned.m8n8.x4.trans.shared.b16 {%0,%1,%2,%3}, [%4];" \
        : "=r"((r)[0]), "=r"((r)[1]), "=r"((r)[2]), "=r"((r)[3]) : "r"(addr))

#define MMA16816(d, a, b0, b1) \
    asm volatile("mma.sync.aligned.m16n8k16.row.col.f32.bf16.bf16.f32 " \
        "{%0,%1,%2,%3}, {%4,%5,%6,%7}, {%8,%9}, {%0,%1,%2,%3};" \
        : "+f"((d)[0]), "+f"((d)[1]), "+f"((d)[2]), "+f"((d)[3]) \
        : "r"((a)[0]), "r"((a)[1]), "r"((a)[2]), "r"((a)[3]), "r"(b0), "r"(b1))

__device__ __forceinline__ uint32_t pk2(float lo, float hi) {
    uint32_t r;
    asm("cvt.rn.bf16x2.f32 %0, %1, %2;" : "=r"(r) : "f"(hi), "f"(lo));
    return r;
}
__device__ __forceinline__ float f2b(float x) {
    return __bfloat162float(__float2bfloat16(x));
}

// ---------------------------------------------------------------------------
// split-bf16 HMMA GEMM: C[128x128] = (Ahi+Alo)(Whi+Wlo)^T + bias
// BM=BN=128, BK=32, 2-stage cp.async, 256 thr. (R5-verified config.)
// splitOut=0: C fp32. splitOut=1: bf16 hi/lo outputs.
// ---------------------------------------------------------------------------
__device__ __forceinline__ void gemm_mma_tile(
    const __nv_bfloat16* __restrict__ Ahi, const __nv_bfloat16* __restrict__ Alo,
    const __nv_bfloat16* __restrict__ Whi, const __nv_bfloat16* __restrict__ Wlo,
    const float* __restrict__ bias, float* __restrict__ C,
    __nv_bfloat16* __restrict__ Chi, __nv_bfloat16* __restrict__ Clo,
    int splitOut)
{
    extern __shared__ __align__(16) char smem[];
    const uint32_t sbase = smem_u32(smem);

    const int tid  = threadIdx.x;
    const int lane = tid & 31;
    const int w    = tid >> 5;
    const int wm   = w & 1;              // 2 m-blocks of 64
    const int wn   = w >> 1;             // 4 n-blocks of 32
    const int rBase = blockIdx.y * 128;
    const int cBase = blockIdx.x * 128;

    const int j = lane >> 3;
    const int l8 = lane & 7;
    const uint32_t a_lane_off =
        (uint32_t)((wm * 64 + (j & 1) * 8 + l8) * TILE_STRIDE + ((j >> 1) * 8) * 2);
    const uint32_t b_lane_off = (uint32_t)(2 * TILE_BYTES +
        (wn * 32 + (j >> 1) * 8 + l8) * TILE_STRIDE + ((j & 1) * 8) * 2);

    float acc[4][4][4];
#pragma unroll
    for (int mt = 0; mt < 4; mt++)
#pragma unroll
        for (int nt = 0; nt < 4; nt++)
#pragma unroll
            for (int e = 0; e < 4; e++) acc[mt][nt][e] = 0.f;

    auto load_stage = [&](int s, int kc) {
        const uint32_t dst0 = sbase + s * STAGE_BYTES;
        const int row = tid >> 2;
        const int c   = tid & 3;
        const __nv_bfloat16* gsrc[4] = { Ahi, Alo, Whi, Wlo };
        const int gRow[4] = { rBase, rBase, cBase, cBase };
#pragma unroll
        for (int t = 0; t < 4; t++) {
#pragma unroll
            for (int half = 0; half < 2; half++) {
                const int r = row + half * 64;
                const __nv_bfloat16* src =
                    gsrc[t] + (size_t)(gRow[t] + r) * KDIM + kc + c * 8;
                const uint32_t dst = dst0 + t * TILE_BYTES + r * TILE_STRIDE + c * 16;
                CP_ASYNC16(dst, src);
            }
        }
    };

    load_stage(0, 0);
    CP_COMMIT();

    for (int i = 0; i < NCHUNK; i++) {
        if (i + 1 < NCHUNK) {
            load_stage((i + 1) & 1, (i + 1) * BK);
            CP_COMMIT();
            CP_WAIT(1);
        } else {
            CP_WAIT(0);
        }
        __syncthreads();

        const uint32_t base = sbase + (i & 1) * STAGE_BYTES;
#pragma unroll
        for (int ks = 0; ks < 2; ks++) {
            const uint32_t koff = ks * 32;
            uint32_t bh[2][4], bl[2][4];
#pragma unroll
            for (int p = 0; p < 2; p++) {
                const uint32_t bo = base + b_lane_off + p * (16 * TILE_STRIDE) + koff;
                LDSM_X4(bh[p], bo);
                LDSM_X4(bl[p], bo + TILE_BYTES);
            }
#pragma unroll
            for (int mt = 0; mt < 4; mt++) {
                uint32_t ah[4], al[4];
                const uint32_t ao = base + a_lane_off + mt * (16 * TILE_STRIDE) + koff;
                LDSM_X4(ah, ao);
                LDSM_X4(al, ao + TILE_BYTES);
#pragma unroll
                for (int nt = 0; nt < 4; nt++) {
                    const int p = nt >> 1, s2 = (nt & 1) * 2;
                    MMA16816(acc[mt][nt], ah, bh[p][s2], bh[p][s2 + 1]);
                    MMA16816(acc[mt][nt], al, bh[p][s2], bh[p][s2 + 1]);
                    MMA16816(acc[mt][nt], ah, bl[p][s2], bl[p][s2 + 1]);
                }
            }
        }
        __syncthreads();
    }

    const int qr = lane >> 2;
    const int qc = (lane & 3) * 2;
#pragma unroll
    for (int mt = 0; mt < 4; mt++) {
#pragma unroll
        for (int nt = 0; nt < 4; nt++) {
            const int row = rBase + wm * 64 + mt * 16 + qr;
            const int col = cBase + wn * 32 + nt * 8 + qc;
            const float b0 = bias[col], b1 = bias[col + 1];
            float v00 = acc[mt][nt][0] + b0, v01 = acc[mt][nt][1] + b1;
            float v10 = acc[mt][nt][2] + b0, v11 = acc[mt][nt][3] + b1;
            if (!splitOut) {
                *(float2*)(C + (size_t)row * EMB + col) = make_float2(v00, v01);
                *(float2*)(C + (size_t)(row + 8) * EMB + col) = make_float2(v10, v11);
            } else {
                float h00 = f2b(v00), h01 = f2b(v01), h10 = f2b(v10), h11 = f2b(v11);
                *(uint32_t*)(Chi + (size_t)row * EMB + col) = pk2(v00, v01);
                *(uint32_t*)(Chi + (size_t)(row + 8) * EMB + col) = pk2(v10, v11);
                *(uint32_t*)(Clo + (size_t)row * EMB + col) = pk2(v00 - h00, v01 - h01);
                *(uint32_t*)(Clo + (size_t)(row + 8) * EMB + col) = pk2(v10 - h10, v11 - h11);
            }
        }
    }
}

__global__ __launch_bounds__(256, 2) void qkv_mma_kernel(
    const __nv_bfloat16* __restrict__ Ahi, const __nv_bfloat16* __restrict__ Alo,
    const __nv_bfloat16* __restrict__ whi, const __nv_bfloat16* __restrict__ wlo,
    const float* __restrict__ qb, const float* __restrict__ kb,
    const float* __restrict__ vb,
    float* __restrict__ Cq, float* __restrict__ Ck,
    __nv_bfloat16* __restrict__ Vhi, __nv_bfloat16* __restrict__ Vlo)
{
    const __nv_bfloat16* Bhi = whi + (size_t)blockIdx.z * EMB * EMB;
    const __nv_bfloat16* Blo = wlo + (size_t)blockIdx.z * EMB * EMB;
    if (blockIdx.z == 0)
        gemm_mma_tile(Ahi, Alo, Bhi, Blo, qb, Cq, nullptr, nullptr, 0);
    else if (blockIdx.z == 1)
        gemm_mma_tile(Ahi, Alo, Bhi, Blo, kb, Ck, nullptr, nullptr, 0);
    else
        gemm_mma_tile(Ahi, Alo, Bhi, Blo, vb, nullptr, Vhi, Vlo, 1);
}

__global__ __launch_bounds__(256, 2) void oproj_mma_kernel(
    const __nv_bfloat16* __restrict__ Ahi, const __nv_bfloat16* __restrict__ Alo,
    const __nv_bfloat16* __restrict__ Bhi, const __nv_bfloat16* __restrict__ Blo,
    const float* __restrict__ bias, float* __restrict__ C)
{
    gemm_mma_tile(Ahi, Alo, Bhi, Blo, bias, C, nullptr, nullptr, 0);
}

// ---------------- batched fp32 -> (bf16 hi, bf16 lo) split ------------------
#define HS8 (S_TOK * EMB / 8)
#define W8  (EMB * EMB / 8)
#define CVT_TOTAL (HS8 + 4 * W8)

__global__ __launch_bounds__(256) void cvt_all_kernel(
    const float* __restrict__ hs, const float* __restrict__ qw,
    const float* __restrict__ kw, const float* __restrict__ vw,
    const float* __restrict__ ow,
    __nv_bfloat16* __restrict__ hshi, __nv_bfloat16* __restrict__ hslo,
    __nv_bfloat16* __restrict__ whi, __nv_bfloat16* __restrict__ wlo)
{
    int t = blockIdx.x * blockDim.x + threadIdx.x;
    if (t >= CVT_TOTAL) return;
    const float* src;
    __nv_bfloat16 *hi, *lo;
    size_t off;
    if (t < HS8) {
        src = hs; hi = hshi; lo = hslo; off = (size_t)t * 8;
    } else {
        int r = t - HS8;
        int wsel = r / W8;
        int loc = r - wsel * W8;
        const float* ws[4] = { qw, kw, vw, ow };
        src = ws[wsel];
        hi = whi + (size_t)wsel * EMB * EMB;
        lo = wlo + (size_t)wsel * EMB * EMB;
        off = (size_t)loc * 8;
    }
    const float4* s4 = (const float4*)(src + off);
    float4 a = s4[0], b = s4[1];
    float v[8] = {a.x, a.y, a.z, a.w, b.x, b.y, b.z, b.w};
    __nv_bfloat16 h[8], l[8];
#pragma unroll
    for (int k = 0; k < 8; k++) {
        h[k] = __float2bfloat16(v[k]);
        l[k] = __float2bfloat16(v[k] - __bfloat162float(h[k]));
    }
    *(uint4*)(hi + off) = *(uint4*)h;
    *(uint4*)(lo + off) = *(uint4*)l;
}

// ---------------- prep: RoPE + (scale) + split Q and K ----------------------
__global__ __launch_bounds__(256) void prep_qk_kernel(
    const float* __restrict__ Q, const float* __restrict__ K,
    __nv_bfloat16* __restrict__ qh, __nv_bfloat16* __restrict__ ql,
    __nv_bfloat16* __restrict__ kh, __nv_bfloat16* __restrict__ kl,
    const float* __restrict__ cosp, const float* __restrict__ sinp)
{
    int idx = blockIdx.x * blockDim.x + threadIdx.x;
    if (idx >= S_TOK * NH * 9) return;
    const int c = idx % 9;
    const int t = idx / 9;
    const int h = t % NH;
    const int s = t / NH;
    const size_t gb = (size_t)s * EMB + h * HD + c * 4;
    const size_t pb = (size_t)s * HD + c * 4;
    const float scale = rsqrtf((float)HD);

    float4 cl = *(const float4*)(cosp + pb);
    float4 sl = *(const float4*)(sinp + pb);
    float4 ch = *(const float4*)(cosp + pb + 36);
    float4 sh = *(const float4*)(sinp + pb + 36);

    {   // Q (scaled)
        float4 a = *(const float4*)(Q + gb);
        float4 b = *(const float4*)(Q + gb + 36);
        float lo4[4] = { (a.x * cl.x - b.x * sl.x) * scale, (a.y * cl.y - b.y * sl.y) * scale,
                         (a.z * cl.z - b.z * sl.z) * scale, (a.w * cl.w - b.w * sl.w) * scale };
        float hi4[4] = { (b.x * ch.x + a.x * sh.x) * scale, (b.y * ch.y + a.y * sh.y) * scale,
                         (b.z * ch.z + a.z * sh.z) * scale, (b.w * ch.w + a.w * sh.w) * scale };
        float lr[4], hr[4];
#pragma unroll
        for (int e = 0; e < 4; e++) { lr[e] = lo4[e] - f2b(lo4[e]); hr[e] = hi4[e] - f2b(hi4[e]); }
        *(uint2*)(qh + gb)      = make_uint2(pk2(lo4[0], lo4[1]), pk2(lo4[2], lo4[3]));
        *(uint2*)(qh + gb + 36) = make_uint2(pk2(hi4[0], hi4[1]), pk2(hi4[2], hi4[3]));
        *(uint2*)(ql + gb)      = make_uint2(pk2(lr[0], lr[1]), pk2(lr[2], lr[3]));
        *(uint2*)(ql + gb + 36) = make_uint2(pk2(hr[0], hr[1]), pk2(hr[2], hr[3]));
    }
    {   // K (unscaled)
        float4 a = *(const float4*)(K + gb);
        float4 b = *(const float4*)(K + gb + 36);
        float lo4[4] = { a.x * cl.x - b.x * sl.x, a.y * cl.y - b.y * sl.y,
                         a.z * cl.z - b.z * sl.z, a.w * cl.w - b.w * sl.w };
        float hi4[4] = { b.x * ch.x + a.x * sh.x, b.y * ch.y + a.y * sh.y,
                         b.z * ch.z + a.z * sh.z, b.w * ch.w + a.w * sh.w };
        float lr[4], hr[4];
#pragma unroll
        for (int e = 0; e < 4; e++) { lr[e] = lo4[e] - f2b(lo4[e]); hr[e] = hi4[e] - f2b(hi4[e]); }
        *(uint2*)(kh + gb)      = make_uint2(pk2(lo4[0], lo4[1]), pk2(lo4[2], lo4[3]));
        *(uint2*)(kh + gb + 36) = make_uint2(pk2(hi4[0], hi4[1]), pk2(hi4[2], hi4[3]));
        *(uint2*)(kl + gb)      = make_uint2(pk2(lr[0], lr[1]), pk2(lr[2], lr[3]));
        *(uint2*)(kl + gb + 36) = make_uint2(pk2(hr[0], hr[1]), pk2(hr[2], hr[3]));
    }
}

// ---------------------------------------------------------------------------
// HMMA flash attention v2 (R7-verified): prepped operands, cp.async 3-stage.
// CTA = (128 queries, 1 head), 8 warps, occ 2.
// ---------------------------------------------------------------------------
__global__ __launch_bounds__(256, 2) void attn_mma_kernel(
    const __nv_bfloat16* __restrict__ QH, const __nv_bfloat16* __restrict__ QL,
    const __nv_bfloat16* __restrict__ KHg, const __nv_bfloat16* __restrict__ KLg,
    const __nv_bfloat16* __restrict__ VHg, const __nv_bfloat16* __restrict__ VLg,
    __nv_bfloat16* __restrict__ Ohi, __nv_bfloat16* __restrict__ Olo,
    const int* __restrict__ cu, int nseg)
{
    extern __shared__ __align__(16) char asmem[];
    const uint32_t sb = smem_u32(asmem);

    const int tid  = threadIdx.x;
    const int lane = tid & 31;
    const int w    = tid >> 5;
    const int h    = blockIdx.y;
    const int q0   = blockIdx.x * 128;

    int segStart = 0, segEnd = S_TOK;
    for (int i = 0; i < nseg; i++) {
        int a = cu[i], b = cu[i + 1];
        if (q0 >= a && q0 < b) { segStart = a; segEnd = b; }
    }
    const int ntiles = (segEnd - segStart + 31) / 32;

    // zero pad bytes (head-dims 72..79) for Q rows AND all 3 KV stage buffers
    for (int i = tid; i < 128; i += 256) {
        *(uint4*)(asmem + AQ_H + i * A_ROWB + 144) = make_uint4(0, 0, 0, 0);
        *(uint4*)(asmem + AQ_L + i * A_ROWB + 144) = make_uint4(0, 0, 0, 0);
    }
    for (int i = tid; i < 3 * 32; i += 256) {
        const int b = i / 32, r = i % 32;
        char* rowp = asmem + AKV0 + b * KVS + r * A_ROWB + 144;
        *(uint4*)(rowp + KO_H) = make_uint4(0, 0, 0, 0);
        *(uint4*)(rowp + KO_L) = make_uint4(0, 0, 0, 0);
        *(uint4*)(rowp + VO_H) = make_uint4(0, 0, 0, 0);
        *(uint4*)(rowp + VO_L) = make_uint4(0, 0, 0, 0);
    }

    // stage Q via cp.async (group 0)
    for (int i = tid; i < 128 * 9; i += 256) {
        const int r = i / 9, c = i % 9;
        const size_t g = (size_t)(q0 + r) * EMB + h * HD + c * 8;
        CP_ASYNC16(sb + AQ_H + r * A_ROWB + c * 16, QH + g);
        CP_ASYNC16(sb + AQ_L + r * A_ROWB + c * 16, QL + g);
    }
    CP_COMMIT();

    auto stage_kv = [&](int tt) {
        const int b = tt % 3;
        const int kt = segStart + tt * 32;
        const uint32_t dst0 = sb + AKV0 + b * KVS;
        for (int i = tid; i < 32 * 9; i += 256) {
            const int r = i / 9, c = i % 9;
            const int key = kt + r;
            if (key < segEnd) {
                const size_t g = (size_t)key * EMB + h * HD + c * 8;
                const uint32_t d = dst0 + r * A_ROWB + c * 16;
                CP_ASYNC16(d + KO_H, KHg + g);
                CP_ASYNC16(d + KO_L, KLg + g);
                CP_ASYNC16(d + VO_H, VHg + g);
                CP_ASYNC16(d + VO_L, VLg + g);
            }
        }
    };

    stage_kv(0); CP_COMMIT();
    if (ntiles > 1) { stage_kv(1); CP_COMMIT(); }

    const int j  = lane >> 3;
    const int l8 = lane & 7;
    const uint32_t q_off  = (uint32_t)((16 * w + (j & 1) * 8 + l8) * A_ROWB + (j >> 1) * 16);
    const uint32_t bs_off = (uint32_t)(((j >> 1) * 8 + l8) * A_ROWB + (j & 1) * 16);
    const uint32_t v_off  = (uint32_t)(((j & 1) * 8 + l8) * A_ROWB + (j >> 1) * 16);

    const int qr = lane >> 2;
    const int lc = lane & 3;

    float acc_o[10][4];
#pragma unroll
    for (int dt = 0; dt < 10; dt++)
#pragma unroll
        for (int e = 0; e < 4; e++) acc_o[dt][e] = 0.f;
    float lsum0 = 0.f, lsum1 = 0.f;

    for (int tt = 0; tt < ntiles; tt++) {
        const int kt = segStart + tt * 32;
        if (tt + 1 < ntiles) { CP_WAIT(1); } else { CP_WAIT(0); }
        __syncthreads();
        if (tt + 2 < ntiles) { stage_kv(tt + 2); CP_COMMIT(); }

        const uint32_t kvb = sb + AKV0 + (tt % 3) * KVS;

        if (kt + 32 > segEnd) {
            for (int i = tid; i < 32 * 9; i += 256) {
                const int r = i / 9, c = i % 9;
                if (kt + r >= segEnd) {
                    char* dp2 = asmem + (kvb - sb) + r * A_ROWB + c * 16;
                    *(uint4*)(dp2 + KO_H) = make_uint4(0, 0, 0, 0);
                    *(uint4*)(dp2 + KO_L) = make_uint4(0, 0, 0, 0);
                    *(uint4*)(dp2 + VO_H) = make_uint4(0, 0, 0, 0);
                    *(uint4*)(dp2 + VO_L) = make_uint4(0, 0, 0, 0);
                }
            }
            __syncthreads();
        }

        // ---- S = Q K^T (3-term split), 32 keys ----------------------------
        float acc_s[4][4];
#pragma unroll
        for (int nt = 0; nt < 4; nt++)
#pragma unroll
            for (int e = 0; e < 4; e++) acc_s[nt][e] = 0.f;

#pragma unroll
        for (int kc = 0; kc < 5; kc++) {
            uint32_t qh[4], ql[4];
            const uint32_t ao = sb + AQ_H + q_off + kc * 32;
            LDSM_X4(qh, ao);
            LDSM_X4(ql, ao + (AQ_L - AQ_H));
#pragma unroll
            for (int np = 0; np < 2; np++) {
                uint32_t bh[4], bl[4];
                const uint32_t bo = kvb + KO_H + bs_off + np * (16 * A_ROWB) + kc * 32;
                LDSM_X4(bh, bo);
                LDSM_X4(bl, bo + (KO_L - KO_H));
                MMA16816(acc_s[2 * np],     qh, bh[0], bh[1]);
                MMA16816(acc_s[2 * np],     ql, bh[0], bh[1]);
                MMA16816(acc_s[2 * np],     qh, bl[0], bl[1]);
                MMA16816(acc_s[2 * np + 1], qh, bh[2], bh[3]);
                MMA16816(acc_s[2 * np + 1], ql, bh[2], bh[3]);
                MMA16816(acc_s[2 * np + 1], qh, bl[2], bl[3]);
            }
        }

        // ---- softmax (unnormalized) + mask --------------------------------
#pragma unroll
        for (int nt = 0; nt < 4; nt++) {
            const int colb = kt + nt * 8 + lc * 2;
            float p0 = (colb     < segEnd) ? __expf(acc_s[nt][0]) : 0.f;
            float p1 = (colb + 1 < segEnd) ? __expf(acc_s[nt][1]) : 0.f;
            float p2 = (colb     < segEnd) ? __expf(acc_s[nt][2]) : 0.f;
            float p3 = (colb + 1 < segEnd) ? __expf(acc_s[nt][3]) : 0.f;
            lsum0 += p0 + p1;
            lsum1 += p2 + p3;
            acc_s[nt][0] = p0; acc_s[nt][1] = p1;
            acc_s[nt][2] = p2; acc_s[nt][3] = p3;
        }

        // ---- O += P V (3-term split) --------------------------------------
#pragma unroll
        for (int kc = 0; kc < 2; kc++) {
            uint32_t pa_h[4], pa_l[4];
            const float* s0 = acc_s[2 * kc];
            const float* s1 = acc_s[2 * kc + 1];
            float h00 = f2b(s0[0]), h01 = f2b(s0[1]), h02 = f2b(s0[2]), h03 = f2b(s0[3]);
            float h10 = f2b(s1[0]), h11 = f2b(s1[1]), h12 = f2b(s1[2]), h13 = f2b(s1[3]);
            pa_h[0] = pk2(h00, h01); pa_h[1] = pk2(h02, h03);
            pa_h[2] = pk2(h10, h11); pa_h[3] = pk2(h12, h13);
            pa_l[0] = pk2(s0[0] - h00, s0[1] - h01); pa_l[1] = pk2(s0[2] - h02, s0[3] - h03);
            pa_l[2] = pk2(s1[0] - h10, s1[1] - h11); pa_l[3] = pk2(s1[2] - h12, s1[3] - h13);
#pragma unroll
            for (int dp = 0; dp < 5; dp++) {
                uint32_t vh[4], vl[4];
                const uint32_t vo = kvb + VO_H + v_off + kc * (16 * A_ROWB) + dp * 32;
                LDSM_X4_T(vh, vo);
                LDSM_X4_T(vl, vo + (VO_L - VO_H));
                MMA16816(acc_o[2 * dp],     pa_h, vh[0], vh[1]);
                MMA16816(acc_o[2 * dp],     pa_l, vh[0], vh[1]);
                MMA16816(acc_o[2 * dp],     pa_h, vl[0], vl[1]);
                MMA16816(acc_o[2 * dp + 1], pa_h, vh[2], vh[3]);
                MMA16816(acc_o[2 * dp + 1], pa_l, vh[2], vh[3]);
                MMA16816(acc_o[2 * dp + 1], pa_h, vl[2], vl[3]);
            }
        }
    }

    // ---- epilogue ---------------------------------------------------------
    lsum0 += __shfl_xor_sync(0xffffffffu, lsum0, 1);
    lsum0 += __shfl_xor_sync(0xffffffffu, lsum0, 2);
    lsum1 += __shfl_xor_sync(0xffffffffu, lsum1, 1);
    lsum1 += __shfl_xor_sync(0xffffffffu, lsum1, 2);
    const float inv0 = 1.0f / lsum0;
    const float inv1 = 1.0f / lsum1;
    const int row0 = q0 + 16 * w + qr;
    const int row1 = row0 + 8;
#pragma unroll
    for (int dt = 0; dt < 9; dt++) {
        const int d = dt * 8 + lc * 2;
        const size_t o0 = (size_t)row0 * EMB + h * HD + d;
        const size_t o1 = (size_t)row1 * EMB + h * HD + d;
        float v00 = acc_o[dt][0] * inv0, v01 = acc_o[dt][1] * inv0;
        float v10 = acc_o[dt][2] * inv1, v11 = acc_o[dt][3] * inv1;
        float h00 = f2b(v00), h01 = f2b(v01), h10 = f2b(v10), h11 = f2b(v11);
        *(uint32_t*)(Ohi + o0) = pk2(v00, v01);
        *(uint32_t*)(Ohi + o1) = pk2(v10, v11);
        *(uint32_t*)(Olo + o0) = pk2(v00 - h00, v01 - h01);
        *(uint32_t*)(Olo + o1) = pk2(v10 - h10, v11 - h11);
    }
}

// ---------------------------------------------------------------------------
extern "C" void kernel_launch(void* const* d_in, const int* in_sizes, int n_in,
                              void* d_out, int out_size)
{
    const float* hs   = (const float*)d_in[0];
    const float* qw   = (const float*)d_in[1];
    const float* qb   = (const float*)d_in[2];
    const float* kw   = (const float*)d_in[3];
    const float* kb   = (const float*)d_in[4];
    const float* vw   = (const float*)d_in[5];
    const float* vb   = (const float*)d_in[6];
    const float* ow   = (const float*)d_in[7];
    const float* ob   = (const float*)d_in[8];
    const float* cosp = (const float*)d_in[9];
    const float* sinp = (const float*)d_in[10];
    const int*   cu   = (const int*)d_in[11];
    const int nseg = in_sizes[11] - 1;

    float *qp, *kp;
    cudaGetSymbolAddress((void**)&qp, g_q);
    cudaGetSymbolAddress((void**)&kp, g_k);
    __nv_bfloat16 *hshi, *hslo, *khi, *klo, *vhi, *vlo, *ahi, *alo, *whi, *wlo;
    cudaGetSymbolAddress((void**)&hshi, g_hs_hi);
    cudaGetSymbolAddress((void**)&hslo, g_hs_lo);
    cudaGetSymbolAddress((void**)&khi, g_k_hi);
    cudaGetSymbolAddress((void**)&klo, g_k_lo);
    cudaGetSymbolAddress((void**)&vhi, g_v_hi);
    cudaGetSymbolAddress((void**)&vlo, g_v_lo);
    cudaGetSymbolAddress((void**)&ahi, g_a_hi);
    cudaGetSymbolAddress((void**)&alo, g_a_lo);
    cudaGetSymbolAddress((void**)&whi, g_w_hi);
    cudaGetSymbolAddress((void**)&wlo, g_w_lo);

    cudaFuncSetAttribute(qkv_mma_kernel,
                         cudaFuncAttributeMaxDynamicSharedMemorySize, GEMM_SMEM);
    cudaFuncSetAttribute(oproj_mma_kernel,
                         cudaFuncAttributeMaxDynamicSharedMemorySize, GEMM_SMEM);
    cudaFuncSetAttribute(attn_mma_kernel,
                         cudaFuncAttributeMaxDynamicSharedMemorySize, ATTN_SMEM);

    // 0) split fp32 -> bf16 hi/lo (hs + 4 weights)
    cvt_all_kernel<<<(CVT_TOTAL + 255) / 256, 256>>>(
        hs, qw, kw, vw, ow, hshi, hslo, whi, wlo);

    // 1) Q/K/V projections (BM=BN=128). V written split directly.
    qkv_mma_kernel<<<dim3(EMB / 128, S_TOK / 128, 3), 256, GEMM_SMEM>>>(
        hshi, hslo, whi, wlo, qb, kb, vb, qp, kp, vhi, vlo);

    // 2) prep: RoPE + scale + split Q/K (reuses hs hi/lo buffers for Q)
    prep_qk_kernel<<<(S_TOK * NH * 9 + 255) / 256, 256>>>(
        qp, kp, hshi, hslo, khi, klo, cosp, sinp);

    // 3) HMMA flash attention (pipelined cp.async staging)
    attn_mma_kernel<<<dim3(S_TOK / 128, NH), 256, ATTN_SMEM>>>(
        hshi, hslo, khi, klo, vhi, vlo, ahi, alo, cu, nseg);

    // 4) O projection -> d_out
    oproj_mma_kernel<<<dim3(EMB / 128, S_TOK / 128), 256, GEMM_SMEM>>>(
        ahi, alo, whi + 3 * (size_t)EMB * EMB, wlo + 3 * (size_t)EMB * EMB,
        ob, (float*)d_out);
}

// round 10
// speedup vs baseline: 1.2867x; 1.1300x over previous
#include <cuda_runtime.h>
#include <cuda_bf16.h>
#include <cuda_fp16.h>
#include <cstdint>
#include <math.h>

#define S_TOK 2048
#define EMB   1152
#define NH    16
#define HD    72
#define KDIM  1152
#define BK    32
#define NCHUNK (KDIM / BK)          // 36
#define TILE_STRIDE 80
#define TILE_BYTES  (128 * TILE_STRIDE)   // 10240
#define STAGE_BYTES (4 * TILE_BYTES)      // 40960
#define GEMM_SMEM  (2 * STAGE_BYTES)      // 81920

// ---- oproj (fp16 1-term, BM=128, BN=64, 3-stage) ----
#define P_A 0
#define P_B 10240
#define P_STAGE 15360
#define OPJ_SMEM (3 * P_STAGE)      // 46080

// ---- attention smem layout ----
#define A_ROWB 176
#define AQ_H 0
#define AQ_L 22528
#define AKV0 45056
#define KVS  22528
#define KO_H 0
#define KO_L 5632
#define VO_H 11264
#define VO_L 16896
#define ATTN_SMEM 112640

// ---------------- scratch ----------------------------------------------------
__device__ float g_q[S_TOK * EMB];
__device__ float g_k[S_TOK * EMB];

__device__ __align__(16) __nv_bfloat16 g_hs_hi[S_TOK * EMB];
__device__ __align__(16) __nv_bfloat16 g_hs_lo[S_TOK * EMB];
__device__ __align__(16) __nv_bfloat16 g_k_hi[S_TOK * EMB];
__device__ __align__(16) __nv_bfloat16 g_k_lo[S_TOK * EMB];
__device__ __align__(16) __nv_bfloat16 g_v_hi[S_TOK * EMB];
__device__ __align__(16) __nv_bfloat16 g_v_lo[S_TOK * EMB];
__device__ __align__(16) __half       g_a_f16[S_TOK * EMB];   // attention out, fp16
__device__ __align__(16) __nv_bfloat16 g_w_hi[4][EMB * EMB];  // [3] holds ow as fp16 (bit-cast)
__device__ __align__(16) __nv_bfloat16 g_w_lo[4][EMB * EMB];

// ---------------- helpers ----------------------------------------------------
__device__ __forceinline__ uint32_t smem_u32(const void* p) {
    uint32_t a;
    asm("{ .reg .u64 t; cvta.to.shared.u64 t, %1; cvt.u32.u64 %0, t; }"
        : "=r"(a) : "l"(p));
    return a;
}

#define CP_ASYNC16(dst, src) \
    asm volatile("cp.async.cg.shared.global [%0], [%1], 16;" :: "r"(dst), "l"(src))
#define CP_COMMIT() asm volatile("cp.async.commit_group;" ::: "memory")
#define CP_WAIT(n)  asm volatile("cp.async.wait_group %0;" :: "n"(n) : "memory")

#define LDSM_X4(r, addr) \
    asm volatile("ldmatrix.sync.aligned.m8n8.x4.shared.b16 {%0,%1,%2,%3}, [%4];" \
        : "=r"((r)[0]), "=r"((r)[1]), "=r"((r)[2]), "=r"((r)[3]) : "r"(addr))
#define LDSM_X4_T(r, addr) \
    asm volatile("ldmatrix.sync.aligned.m8n8.x4.trans.shared.b16 {%0,%1,%2,%3}, [%4];" \
        : "=r"((r)[0]), "=r"((r)[1]), "=r"((r)[2]), "=r"((r)[3]) : "r"(addr))

#define MMA16816(d, a, b0, b1) \
    asm volatile("mma.sync.aligned.m16n8k16.row.col.f32.bf16.bf16.f32 " \
        "{%0,%1,%2,%3}, {%4,%5,%6,%7}, {%8,%9}, {%0,%1,%2,%3};" \
        : "+f"((d)[0]), "+f"((d)[1]), "+f"((d)[2]), "+f"((d)[3]) \
        : "r"((a)[0]), "r"((a)[1]), "r"((a)[2]), "r"((a)[3]), "r"(b0), "r"(b1))

#define MMA16816H(d, a, b0, b1) \
    asm volatile("mma.sync.aligned.m16n8k16.row.col.f32.f16.f16.f32 " \
        "{%0,%1,%2,%3}, {%4,%5,%6,%7}, {%8,%9}, {%0,%1,%2,%3};" \
        : "+f"((d)[0]), "+f"((d)[1]), "+f"((d)[2]), "+f"((d)[3]) \
        : "r"((a)[0]), "r"((a)[1]), "r"((a)[2]), "r"((a)[3]), "r"(b0), "r"(b1))

__device__ __forceinline__ uint32_t pk2(float lo, float hi) {
    uint32_t r;
    asm("cvt.rn.bf16x2.f32 %0, %1, %2;" : "=r"(r) : "f"(hi), "f"(lo));
    return r;
}
__device__ __forceinline__ uint32_t pk2h(float lo, float hi) {
    uint32_t r;
    asm("cvt.rn.f16x2.f32 %0, %1, %2;" : "=r"(r) : "f"(hi), "f"(lo));
    return r;
}
__device__ __forceinline__ float f2b(float x) {
    return __bfloat162float(__float2bfloat16(x));
}

// ---------------------------------------------------------------------------
// split-bf16 HMMA GEMM (R5/R8-verified): BM=BN=128, BK=32, 2-stage.
// ---------------------------------------------------------------------------
__device__ __forceinline__ void gemm_mma_tile(
    const __nv_bfloat16* __restrict__ Ahi, const __nv_bfloat16* __restrict__ Alo,
    const __nv_bfloat16* __restrict__ Whi, const __nv_bfloat16* __restrict__ Wlo,
    const float* __restrict__ bias, float* __restrict__ C,
    __nv_bfloat16* __restrict__ Chi, __nv_bfloat16* __restrict__ Clo,
    int splitOut)
{
    extern __shared__ __align__(16) char smem[];
    const uint32_t sbase = smem_u32(smem);

    const int tid  = threadIdx.x;
    const int lane = tid & 31;
    const int w    = tid >> 5;
    const int wm   = w & 1;
    const int wn   = w >> 1;
    const int rBase = blockIdx.y * 128;
    const int cBase = blockIdx.x * 128;

    const int j = lane >> 3;
    const int l8 = lane & 7;
    const uint32_t a_lane_off =
        (uint32_t)((wm * 64 + (j & 1) * 8 + l8) * TILE_STRIDE + ((j >> 1) * 8) * 2);
    const uint32_t b_lane_off = (uint32_t)(2 * TILE_BYTES +
        (wn * 32 + (j >> 1) * 8 + l8) * TILE_STRIDE + ((j & 1) * 8) * 2);

    float acc[4][4][4];
#pragma unroll
    for (int mt = 0; mt < 4; mt++)
#pragma unroll
        for (int nt = 0; nt < 4; nt++)
#pragma unroll
            for (int e = 0; e < 4; e++) acc[mt][nt][e] = 0.f;

    auto load_stage = [&](int s, int kc) {
        const uint32_t dst0 = sbase + s * STAGE_BYTES;
        const int row = tid >> 2;
        const int c   = tid & 3;
        const __nv_bfloat16* gsrc[4] = { Ahi, Alo, Whi, Wlo };
        const int gRow[4] = { rBase, rBase, cBase, cBase };
#pragma unroll
        for (int t = 0; t < 4; t++) {
#pragma unroll
            for (int half = 0; half < 2; half++) {
                const int r = row + half * 64;
                const __nv_bfloat16* src =
                    gsrc[t] + (size_t)(gRow[t] + r) * KDIM + kc + c * 8;
                const uint32_t dst = dst0 + t * TILE_BYTES + r * TILE_STRIDE + c * 16;
                CP_ASYNC16(dst, src);
            }
        }
    };

    load_stage(0, 0);
    CP_COMMIT();

    for (int i = 0; i < NCHUNK; i++) {
        if (i + 1 < NCHUNK) {
            load_stage((i + 1) & 1, (i + 1) * BK);
            CP_COMMIT();
            CP_WAIT(1);
        } else {
            CP_WAIT(0);
        }
        __syncthreads();

        const uint32_t base = sbase + (i & 1) * STAGE_BYTES;
#pragma unroll
        for (int ks = 0; ks < 2; ks++) {
            const uint32_t koff = ks * 32;
            uint32_t bh[2][4], bl[2][4];
#pragma unroll
            for (int p = 0; p < 2; p++) {
                const uint32_t bo = base + b_lane_off + p * (16 * TILE_STRIDE) + koff;
                LDSM_X4(bh[p], bo);
                LDSM_X4(bl[p], bo + TILE_BYTES);
            }
#pragma unroll
            for (int mt = 0; mt < 4; mt++) {
                uint32_t ah[4], al[4];
                const uint32_t ao = base + a_lane_off + mt * (16 * TILE_STRIDE) + koff;
                LDSM_X4(ah, ao);
                LDSM_X4(al, ao + TILE_BYTES);
#pragma unroll
                for (int nt = 0; nt < 4; nt++) {
                    const int p = nt >> 1, s2 = (nt & 1) * 2;
                    MMA16816(acc[mt][nt], ah, bh[p][s2], bh[p][s2 + 1]);
                    MMA16816(acc[mt][nt], al, bh[p][s2], bh[p][s2 + 1]);
                    MMA16816(acc[mt][nt], ah, bl[p][s2], bl[p][s2 + 1]);
                }
            }
        }
        __syncthreads();
    }

    const int qr = lane >> 2;
    const int qc = (lane & 3) * 2;
#pragma unroll
    for (int mt = 0; mt < 4; mt++) {
#pragma unroll
        for (int nt = 0; nt < 4; nt++) {
            const int row = rBase + wm * 64 + mt * 16 + qr;
            const int col = cBase + wn * 32 + nt * 8 + qc;
            const float b0 = bias[col], b1 = bias[col + 1];
            float v00 = acc[mt][nt][0] + b0, v01 = acc[mt][nt][1] + b1;
            float v10 = acc[mt][nt][2] + b0, v11 = acc[mt][nt][3] + b1;
            if (!splitOut) {
                *(float2*)(C + (size_t)row * EMB + col) = make_float2(v00, v01);
                *(float2*)(C + (size_t)(row + 8) * EMB + col) = make_float2(v10, v11);
            } else {
                float h00 = f2b(v00), h01 = f2b(v01), h10 = f2b(v10), h11 = f2b(v11);
                *(uint32_t*)(Chi + (size_t)row * EMB + col) = pk2(v00, v01);
                *(uint32_t*)(Chi + (size_t)(row + 8) * EMB + col) = pk2(v10, v11);
                *(uint32_t*)(Clo + (size_t)row * EMB + col) = pk2(v00 - h00, v01 - h01);
                *(uint32_t*)(Clo + (size_t)(row + 8) * EMB + col) = pk2(v10 - h10, v11 - h11);
            }
        }
    }
}

__global__ __launch_bounds__(256, 2) void qkv_mma_kernel(
    const __nv_bfloat16* __restrict__ Ahi, const __nv_bfloat16* __restrict__ Alo,
    const __nv_bfloat16* __restrict__ whi, const __nv_bfloat16* __restrict__ wlo,
    const float* __restrict__ qb, const float* __restrict__ kb,
    const float* __restrict__ vb,
    float* __restrict__ Cq, float* __restrict__ Ck,
    __nv_bfloat16* __restrict__ Vhi, __nv_bfloat16* __restrict__ Vlo)
{
    const __nv_bfloat16* Bhi = whi + (size_t)blockIdx.z * EMB * EMB;
    const __nv_bfloat16* Blo = wlo + (size_t)blockIdx.z * EMB * EMB;
    if (blockIdx.z == 0)
        gemm_mma_tile(Ahi, Alo, Bhi, Blo, qb, Cq, nullptr, nullptr, 0);
    else if (blockIdx.z == 1)
        gemm_mma_tile(Ahi, Alo, Bhi, Blo, kb, Ck, nullptr, nullptr, 0);
    else
        gemm_mma_tile(Ahi, Alo, Bhi, Blo, vb, nullptr, Vhi, Vlo, 1);
}

// ---------------------------------------------------------------------------
// oproj: fp16 1-term GEMM. BM=128, BN=64, BK=32, 3-stage cp.async, 1 sync.
// ---------------------------------------------------------------------------
__global__ __launch_bounds__(256, 2) void oproj_f16_kernel(
    const __half* __restrict__ A,      // [S, EMB] fp16
    const __half* __restrict__ W,      // [EMB, EMB] fp16, K-major
    const float* __restrict__ bias, float* __restrict__ C)
{
    extern __shared__ __align__(16) char smem[];
    const uint32_t sbase = smem_u32(smem);

    const int tid  = threadIdx.x;
    const int lane = tid & 31;
    const int w    = tid >> 5;
    const int wm   = w & 3;
    const int wn   = w >> 2;
    const int rBase = blockIdx.y * 128;
    const int cBase = blockIdx.x * 64;

    const int j  = lane >> 3;
    const int l8 = lane & 7;
    const uint32_t a_lane_off =
        (uint32_t)((wm * 32 + (j & 1) * 8 + l8) * 80 + (j >> 1) * 16);
    const uint32_t b_lane_off =
        (uint32_t)((wn * 32 + (j >> 1) * 8 + l8) * 80 + (j & 1) * 16);

    float acc[2][4][4];
#pragma unroll
    for (int mt = 0; mt < 2; mt++)
#pragma unroll
        for (int nt = 0; nt < 4; nt++)
#pragma unroll
            for (int e = 0; e < 4; e++) acc[mt][nt][e] = 0.f;

    auto load_stage = [&](int s, int kc) {
        const uint32_t dst0 = sbase + s * P_STAGE;
        {
            const int r = tid >> 1, c0 = (tid & 1) * 2;
            const size_t g = (size_t)(rBase + r) * KDIM + kc + c0 * 8;
            const uint32_t d = dst0 + P_A + r * 80 + c0 * 16;
            CP_ASYNC16(d,      A + g);
            CP_ASYNC16(d + 16, A + g + 8);
        }
        {
            const int r = tid >> 2, c = tid & 3;
            const size_t g = (size_t)(cBase + r) * KDIM + kc + c * 8;
            CP_ASYNC16(dst0 + P_B + r * 80 + c * 16, W + g);
        }
    };

    load_stage(0, 0); CP_COMMIT();
    load_stage(1, BK); CP_COMMIT();

    for (int i = 0; i < NCHUNK; i++) {
        if (i + 1 < NCHUNK) { CP_WAIT(1); } else { CP_WAIT(0); }
        __syncthreads();
        if (i + 2 < NCHUNK) {
            load_stage((i + 2) % 3, (i + 2) * BK);
            CP_COMMIT();
        }

        const uint32_t base = sbase + (i % 3) * P_STAGE;
#pragma unroll
        for (int ks = 0; ks < 2; ks++) {
            const uint32_t koff = ks * 32;
            uint32_t bh[2][4];
#pragma unroll
            for (int p = 0; p < 2; p++)
                LDSM_X4(bh[p], base + P_B + b_lane_off + p * 1280 + koff);
#pragma unroll
            for (int mt = 0; mt < 2; mt++) {
                uint32_t ah[4];
                LDSM_X4(ah, base + P_A + a_lane_off + mt * 1280 + koff);
#pragma unroll
                for (int nt = 0; nt < 4; nt++) {
                    const int p = nt >> 1, s2 = (nt & 1) * 2;
                    MMA16816H(acc[mt][nt], ah, bh[p][s2], bh[p][s2 + 1]);
                }
            }
        }
    }

    const int qr = lane >> 2;
    const int qc = (lane & 3) * 2;
#pragma unroll
    for (int mt = 0; mt < 2; mt++) {
#pragma unroll
        for (int nt = 0; nt < 4; nt++) {
            const int row = rBase + wm * 32 + mt * 16 + qr;
            const int col = cBase + wn * 32 + nt * 8 + qc;
            const float b0 = bias[col], b1 = bias[col + 1];
            *(float2*)(C + (size_t)row * EMB + col) =
                make_float2(acc[mt][nt][0] + b0, acc[mt][nt][1] + b1);
            *(float2*)(C + (size_t)(row + 8) * EMB + col) =
                make_float2(acc[mt][nt][2] + b0, acc[mt][nt][3] + b1);
        }
    }
}

// ---------------- batched fp32 conversions ----------------------------------
#define HS8 (S_TOK * EMB / 8)
#define W8  (EMB * EMB / 8)
#define CVT_TOTAL (HS8 + 4 * W8)

__global__ __launch_bounds__(256) void cvt_all_kernel(
    const float* __restrict__ hs, const float* __restrict__ qw,
    const float* __restrict__ kw, const float* __restrict__ vw,
    const float* __restrict__ ow,
    __nv_bfloat16* __restrict__ hshi, __nv_bfloat16* __restrict__ hslo,
    __nv_bfloat16* __restrict__ whi, __nv_bfloat16* __restrict__ wlo)
{
    int t = blockIdx.x * blockDim.x + threadIdx.x;
    if (t >= CVT_TOTAL) return;
    const float* src;
    __nv_bfloat16 *hi, *lo;
    size_t off;
    int wsel = -1;
    if (t < HS8) {
        src = hs; hi = hshi; lo = hslo; off = (size_t)t * 8;
    } else {
        int r = t - HS8;
        wsel = r / W8;
        int loc = r - wsel * W8;
        const float* ws[4] = { qw, kw, vw, ow };
        src = ws[wsel];
        hi = whi + (size_t)wsel * EMB * EMB;
        lo = wlo + (size_t)wsel * EMB * EMB;
        off = (size_t)loc * 8;
    }
    const float4* s4 = (const float4*)(src + off);
    float4 a = s4[0], b = s4[1];
    float v[8] = {a.x, a.y, a.z, a.w, b.x, b.y, b.z, b.w};
    if (wsel == 3) {
        uint32_t p[4];
#pragma unroll
        for (int k = 0; k < 4; k++) p[k] = pk2h(v[2 * k], v[2 * k + 1]);
        *(uint4*)(hi + off) = make_uint4(p[0], p[1], p[2], p[3]);
    } else {
        __nv_bfloat16 h[8], l[8];
#pragma unroll
        for (int k = 0; k < 8; k++) {
            h[k] = __float2bfloat16(v[k]);
            l[k] = __float2bfloat16(v[k] - __bfloat162float(h[k]));
        }
        *(uint4*)(hi + off) = *(uint4*)h;
        *(uint4*)(lo + off) = *(uint4*)l;
    }
}

// ---------------- prep: RoPE + (scale) + split Q and K ----------------------
__global__ __launch_bounds__(256) void prep_qk_kernel(
    const float* __restrict__ Q, const float* __restrict__ K,
    __nv_bfloat16* __restrict__ qh, __nv_bfloat16* __restrict__ ql,
    __nv_bfloat16* __restrict__ kh, __nv_bfloat16* __restrict__ kl,
    const float* __restrict__ cosp, const float* __restrict__ sinp)
{
    int idx = blockIdx.x * blockDim.x + threadIdx.x;
    if (idx >= S_TOK * NH * 9) return;
    const int c = idx % 9;
    const int t = idx / 9;
    const int h = t % NH;
    const int s = t / NH;
    const size_t gb = (size_t)s * EMB + h * HD + c * 4;
    const size_t pb = (size_t)s * HD + c * 4;
    const float scale = rsqrtf((float)HD);

    float4 cl = *(const float4*)(cosp + pb);
    float4 sl = *(const float4*)(sinp + pb);
    float4 ch = *(const float4*)(cosp + pb + 36);
    float4 sh = *(const float4*)(sinp + pb + 36);

    {   // Q (scaled)
        float4 a = *(const float4*)(Q + gb);
        float4 b = *(const float4*)(Q + gb + 36);
        float lo4[4] = { (a.x * cl.x - b.x * sl.x) * scale, (a.y * cl.y - b.y * sl.y) * scale,
                         (a.z * cl.z - b.z * sl.z) * scale, (a.w * cl.w - b.w * sl.w) * scale };
        float hi4[4] = { (b.x * ch.x + a.x * sh.x) * scale, (b.y * ch.y + a.y * sh.y) * scale,
                         (b.z * ch.z + a.z * sh.z) * scale, (b.w * ch.w + a.w * sh.w) * scale };
        float lr[4], hr[4];
#pragma unroll
        for (int e = 0; e < 4; e++) { lr[e] = lo4[e] - f2b(lo4[e]); hr[e] = hi4[e] - f2b(hi4[e]); }
        *(uint2*)(qh + gb)      = make_uint2(pk2(lo4[0], lo4[1]), pk2(lo4[2], lo4[3]));
        *(uint2*)(qh + gb + 36) = make_uint2(pk2(hi4[0], hi4[1]), pk2(hi4[2], hi4[3]));
        *(uint2*)(ql + gb)      = make_uint2(pk2(lr[0], lr[1]), pk2(lr[2], lr[3]));
        *(uint2*)(ql + gb + 36) = make_uint2(pk2(hr[0], hr[1]), pk2(hr[2], hr[3]));
    }
    {   // K (unscaled)
        float4 a = *(const float4*)(K + gb);
        float4 b = *(const float4*)(K + gb + 36);
        float lo4[4] = { a.x * cl.x - b.x * sl.x, a.y * cl.y - b.y * sl.y,
                         a.z * cl.z - b.z * sl.z, a.w * cl.w - b.w * sl.w };
        float hi4[4] = { b.x * ch.x + a.x * sh.x, b.y * ch.y + a.y * sh.y,
                         b.z * ch.z + a.z * sh.z, b.w * ch.w + a.w * sh.w };
        float lr[4], hr[4];
#pragma unroll
        for (int e = 0; e < 4; e++) { lr[e] = lo4[e] - f2b(lo4[e]); hr[e] = hi4[e] - f2b(hi4[e]); }
        *(uint2*)(kh + gb)      = make_uint2(pk2(lo4[0], lo4[1]), pk2(lo4[2], lo4[3]));
        *(uint2*)(kh + gb + 36) = make_uint2(pk2(hi4[0], hi4[1]), pk2(hi4[2], hi4[3]));
        *(uint2*)(kl + gb)      = make_uint2(pk2(lr[0], lr[1]), pk2(lr[2], lr[3]));
        *(uint2*)(kl + gb + 36) = make_uint2(pk2(hr[0], hr[1]), pk2(hr[2], hr[3]));
    }
}

// ---------------------------------------------------------------------------
// HMMA flash attention (R7/R8-verified), output fp16 single.
// ---------------------------------------------------------------------------
__global__ __launch_bounds__(256, 2) void attn_mma_kernel(
    const __nv_bfloat16* __restrict__ QH, const __nv_bfloat16* __restrict__ QL,
    const __nv_bfloat16* __restrict__ KHg, const __nv_bfloat16* __restrict__ KLg,
    const __nv_bfloat16* __restrict__ VHg, const __nv_bfloat16* __restrict__ VLg,
    __half* __restrict__ O16,
    const int* __restrict__ cu, int nseg)
{
    extern __shared__ __align__(16) char asmem[];
    const uint32_t sb = smem_u32(asmem);

    const int tid  = threadIdx.x;
    const int lane = tid & 31;
    const int w    = tid >> 5;
    const int h    = blockIdx.y;
    const int q0   = blockIdx.x * 128;

    int segStart = 0, segEnd = S_TOK;
    for (int i = 0; i < nseg; i++) {
        int a = cu[i], b = cu[i + 1];
        if (q0 >= a && q0 < b) { segStart = a; segEnd = b; }
    }
    const int ntiles = (segEnd - segStart + 31) / 32;

    // zero pad bytes (dims 72..79) for Q rows AND all 3 KV stage buffers
    for (int i = tid; i < 128; i += 256) {
        *(uint4*)(asmem + AQ_H + i * A_ROWB + 144) = make_uint4(0, 0, 0, 0);
        *(uint4*)(asmem + AQ_L + i * A_ROWB + 144) = make_uint4(0, 0, 0, 0);
    }
    for (int i = tid; i < 3 * 32; i += 256) {
        const int b = i / 32, r = i % 32;
        char* rowp = asmem + AKV0 + b * KVS + r * A_ROWB + 144;
        *(uint4*)(rowp + KO_H) = make_uint4(0, 0, 0, 0);
        *(uint4*)(rowp + KO_L) = make_uint4(0, 0, 0, 0);
        *(uint4*)(rowp + VO_H) = make_uint4(0, 0, 0, 0);
        *(uint4*)(rowp + VO_L) = make_uint4(0, 0, 0, 0);
    }

    for (int i = tid; i < 128 * 9; i += 256) {
        const int r = i / 9, c = i % 9;
        const size_t g = (size_t)(q0 + r) * EMB + h * HD + c * 8;
        CP_ASYNC16(sb + AQ_H + r * A_ROWB + c * 16, QH + g);
        CP_ASYNC16(sb + AQ_L + r * A_ROWB + c * 16, QL + g);
    }
    CP_COMMIT();

    auto stage_kv = [&](int tt) {
        const int b = tt % 3;
        const int kt = segStart + tt * 32;
        const uint32_t dst0 = sb + AKV0 + b * KVS;
        for (int i = tid; i < 32 * 9; i += 256) {
            const int r = i / 9, c = i % 9;
            const int key = kt + r;
            if (key < segEnd) {
                const size_t g = (size_t)key * EMB + h * HD + c * 8;
                const uint32_t d = dst0 + r * A_ROWB + c * 16;
                CP_ASYNC16(d + KO_H, KHg + g);
                CP_ASYNC16(d + KO_L, KLg + g);
                CP_ASYNC16(d + VO_H, VHg + g);
                CP_ASYNC16(d + VO_L, VLg + g);
            }
        }
    };

    stage_kv(0); CP_COMMIT();
    if (ntiles > 1) { stage_kv(1); CP_COMMIT(); }

    const int j  = lane >> 3;
    const int l8 = lane & 7;
    const uint32_t q_off  = (uint32_t)((16 * w + (j & 1) * 8 + l8) * A_ROWB + (j >> 1) * 16);
    const uint32_t bs_off = (uint32_t)(((j >> 1) * 8 + l8) * A_ROWB + (j & 1) * 16);
    const uint32_t v_off  = (uint32_t)(((j & 1) * 8 + l8) * A_ROWB + (j >> 1) * 16);

    const int qr = lane >> 2;
    const int lc = lane & 3;

    float acc_o[10][4];
#pragma unroll
    for (int dt = 0; dt < 10; dt++)
#pragma unroll
        for (int e = 0; e < 4; e++) acc_o[dt][e] = 0.f;
    float lsum0 = 0.f, lsum1 = 0.f;

    for (int tt = 0; tt < ntiles; tt++) {
        const int kt = segStart + tt * 32;
        if (tt + 1 < ntiles) { CP_WAIT(1); } else { CP_WAIT(0); }
        __syncthreads();
        if (tt + 2 < ntiles) { stage_kv(tt + 2); CP_COMMIT(); }

        const uint32_t kvb = sb + AKV0 + (tt % 3) * KVS;

        if (kt + 32 > segEnd) {
            for (int i = tid; i < 32 * 9; i += 256) {
                const int r = i / 9, c = i % 9;
                if (kt + r >= segEnd) {
                    char* dp2 = asmem + (kvb - sb) + r * A_ROWB + c * 16;
                    *(uint4*)(dp2 + KO_H) = make_uint4(0, 0, 0, 0);
                    *(uint4*)(dp2 + KO_L) = make_uint4(0, 0, 0, 0);
                    *(uint4*)(dp2 + VO_H) = make_uint4(0, 0, 0, 0);
                    *(uint4*)(dp2 + VO_L) = make_uint4(0, 0, 0, 0);
                }
            }
            __syncthreads();
        }

        float acc_s[4][4];
#pragma unroll
        for (int nt = 0; nt < 4; nt++)
#pragma unroll
            for (int e = 0; e < 4; e++) acc_s[nt][e] = 0.f;

#pragma unroll
        for (int kc = 0; kc < 5; kc++) {
            uint32_t qh[4], ql[4];
            const uint32_t ao = sb + AQ_H + q_off + kc * 32;
            LDSM_X4(qh, ao);
            LDSM_X4(ql, ao + (AQ_L - AQ_H));
#pragma unroll
            for (int np = 0; np < 2; np++) {
                uint32_t bh[4], bl[4];
                const uint32_t bo = kvb + KO_H + bs_off + np * (16 * A_ROWB) + kc * 32;
                LDSM_X4(bh, bo);
                LDSM_X4(bl, bo + (KO_L - KO_H));
                MMA16816(acc_s[2 * np],     qh, bh[0], bh[1]);
                MMA16816(acc_s[2 * np],     ql, bh[0], bh[1]);
                MMA16816(acc_s[2 * np],     qh, bl[0], bl[1]);
                MMA16816(acc_s[2 * np + 1], qh, bh[2], bh[3]);
                MMA16816(acc_s[2 * np + 1], ql, bh[2], bh[3]);
                MMA16816(acc_s[2 * np + 1], qh, bl[2], bl[3]);
            }
        }

#pragma unroll
        for (int nt = 0; nt < 4; nt++) {
            const int colb = kt + nt * 8 + lc * 2;
            float p0 = (colb     < segEnd) ? __expf(acc_s[nt][0]) : 0.f;
            float p1 = (colb + 1 < segEnd) ? __expf(acc_s[nt][1]) : 0.f;
            float p2 = (colb     < segEnd) ? __expf(acc_s[nt][2]) : 0.f;
            float p3 = (colb + 1 < segEnd) ? __expf(acc_s[nt][3]) : 0.f;
            lsum0 += p0 + p1;
            lsum1 += p2 + p3;
            acc_s[nt][0] = p0; acc_s[nt][1] = p1;
            acc_s[nt][2] = p2; acc_s[nt][3] = p3;
        }

#pragma unroll
        for (int kc = 0; kc < 2; kc++) {
            uint32_t pa_h[4], pa_l[4];
            const float* s0 = acc_s[2 * kc];
            const float* s1 = acc_s[2 * kc + 1];
            float h00 = f2b(s0[0]), h01 = f2b(s0[1]), h02 = f2b(s0[2]), h03 = f2b(s0[3]);
            float h10 = f2b(s1[0]), h11 = f2b(s1[1]), h12 = f2b(s1[2]), h13 = f2b(s1[3]);
            pa_h[0] = pk2(h00, h01); pa_h[1] = pk2(h02, h03);
            pa_h[2] = pk2(h10, h11); pa_h[3] = pk2(h12, h13);
            pa_l[0] = pk2(s0[0] - h00, s0[1] - h01); pa_l[1] = pk2(s0[2] - h02, s0[3] - h03);
            pa_l[2] = pk2(s1[0] - h10, s1[1] - h11); pa_l[3] = pk2(s1[2] - h12, s1[3] - h13);
#pragma unroll
            for (int dp = 0; dp < 5; dp++) {
                uint32_t vh[4], vl[4];
                const uint32_t vo = kvb + VO_H + v_off + kc * (16 * A_ROWB) + dp * 32;
                LDSM_X4_T(vh, vo);
                LDSM_X4_T(vl, vo + (VO_L - VO_H));
                MMA16816(acc_o[2 * dp],     pa_h, vh[0], vh[1]);
                MMA16816(acc_o[2 * dp],     pa_l, vh[0], vh[1]);
                MMA16816(acc_o[2 * dp],     pa_h, vl[0], vl[1]);
                MMA16816(acc_o[2 * dp + 1], pa_h, vh[2], vh[3]);
                MMA16816(acc_o[2 * dp + 1], pa_l, vh[2], vh[3]);
                MMA16816(acc_o[2 * dp + 1], pa_h, vl[2], vl[3]);
            }
        }
    }

    // ---- epilogue: normalize, write fp16 ---------------------------------
    lsum0 += __shfl_xor_sync(0xffffffffu, lsum0, 1);
    lsum0 += __shfl_xor_sync(0xffffffffu, lsum0, 2);
    lsum1 += __shfl_xor_sync(0xffffffffu, lsum1, 1);
    lsum1 += __shfl_xor_sync(0xffffffffu, lsum1, 2);
    const float inv0 = 1.0f / lsum0;
    const float inv1 = 1.0f / lsum1;
    const int row0 = q0 + 16 * w + qr;
    const int row1 = row0 + 8;
#pragma unroll
    for (int dt = 0; dt < 9; dt++) {
        const int d = dt * 8 + lc * 2;
        *(uint32_t*)(O16 + (size_t)row0 * EMB + h * HD + d) =
            pk2h(acc_o[dt][0] * inv0, acc_o[dt][1] * inv0);
        *(uint32_t*)(O16 + (size_t)row1 * EMB + h * HD + d) =
            pk2h(acc_o[dt][2] * inv1, acc_o[dt][3] * inv1);
    }
}

// ---------------------------------------------------------------------------
extern "C" void kernel_launch(void* const* d_in, const int* in_sizes, int n_in,
                              void* d_out, int out_size)
{
    const float* hs   = (const float*)d_in[0];
    const float* qw   = (const float*)d_in[1];
    const float* qb   = (const float*)d_in[2];
    const float* kw   = (const float*)d_in[3];
    const float* kb   = (const float*)d_in[4];
    const float* vw   = (const float*)d_in[5];
    const float* vb   = (const float*)d_in[6];
    const float* ow   = (const float*)d_in[7];
    const float* ob   = (const float*)d_in[8];
    const float* cosp = (const float*)d_in[9];
    const float* sinp = (const float*)d_in[10];
    const int*   cu   = (const int*)d_in[11];
    const int nseg = in_sizes[11] - 1;

    float *qp, *kp;
    cudaGetSymbolAddress((void**)&qp, g_q);
    cudaGetSymbolAddress((void**)&kp, g_k);
    __nv_bfloat16 *hshi, *hslo, *khi, *klo, *vhi, *vlo, *whi, *wlo;
    __half* a16;
    cudaGetSymbolAddress((void**)&hshi, g_hs_hi);
    cudaGetSymbolAddress((void**)&hslo, g_hs_lo);
    cudaGetSymbolAddress((void**)&khi, g_k_hi);
    cudaGetSymbolAddress((void**)&klo, g_k_lo);
    cudaGetSymbolAddress((void**)&vhi, g_v_hi);
    cudaGetSymbolAddress((void**)&vlo, g_v_lo);
    cudaGetSymbolAddress((void**)&a16, g_a_f16);
    cudaGetSymbolAddress((void**)&whi, g_w_hi);
    cudaGetSymbolAddress((void**)&wlo, g_w_lo);

    cudaFuncSetAttribute(qkv_mma_kernel,
                         cudaFuncAttributeMaxDynamicSharedMemorySize, GEMM_SMEM);
    cudaFuncSetAttribute(oproj_f16_kernel,
                         cudaFuncAttributeMaxDynamicSharedMemorySize, OPJ_SMEM);
    cudaFuncSetAttribute(attn_mma_kernel,
                         cudaFuncAttributeMaxDynamicSharedMemorySize, ATTN_SMEM);

    // 0) conversions: hs/qw/kw/vw -> bf16 hi/lo; ow -> fp16 (in whi[3])
    cvt_all_kernel<<<(CVT_TOTAL + 255) / 256, 256>>>(
        hs, qw, kw, vw, ow, hshi, hslo, whi, wlo);

    // 1) Q/K/V projections (bf16 3-term). V written split.
    qkv_mma_kernel<<<dim3(EMB / 128, S_TOK / 128, 3), 256, GEMM_SMEM>>>(
        hshi, hslo, whi, wlo, qb, kb, vb, qp, kp, vhi, vlo);

    // 2) prep: RoPE + scale + split Q/K
    prep_qk_kernel<<<(S_TOK * NH * 9 + 255) / 256, 256>>>(
        qp, kp, hshi, hslo, khi, klo, cosp, sinp);

    // 3) HMMA flash attention -> fp16 output
    attn_mma_kernel<<<dim3(S_TOK / 128, NH), 256, ATTN_SMEM>>>(
        hshi, hslo, khi, klo, vhi, vlo, a16, cu, nseg);

    // 4) O projection (fp16 1-term) -> d_out
    oproj_f16_kernel<<<dim3(EMB / 64, S_TOK / 128), 256, OPJ_SMEM>>>(
        a16, (const __half*)(whi + 3 * (size_t)EMB * EMB), ob, (float*)d_out);
}

// round 11
// speedup vs baseline: 1.4791x; 1.1495x over previous
#include <cuda_runtime.h>
#include <cuda_bf16.h>
#include <cuda_fp16.h>
#include <cstdint>
#include <math.h>

#define S_TOK 2048
#define EMB   1152
#define NH    16
#define HD    72
#define KDIM  1152
#define BK    32
#define NCHUNK (KDIM / BK)          // 36
#define TILE_STRIDE 80
#define TILE_BYTES  (128 * TILE_STRIDE)   // 10240
#define STAGE_BYTES (4 * TILE_BYTES)      // 40960
#define GEMM_SMEM  (2 * STAGE_BYTES)      // 81920

// ---- fp16 1-term GEMM (oproj / vproj): BM=128, BN=64, 3-stage ----
#define P_A 0
#define P_B 10240
#define P_STAGE 15360
#define OPJ_SMEM (3 * P_STAGE)      // 46080

// ---- attention smem: Q split bf16 + 3 KV stages (K split bf16, V fp16) ----
#define A_ROWB 176
#define AQ_H 0
#define AQ_L 22528
#define AKV0 45056
#define KO_H 0
#define KO_L 5632
#define VO   11264
#define KVS  16896
#define ATTN_SMEM (45056 + 3 * KVS)   // 95744

// ---------------- scratch ----------------------------------------------------
__device__ float g_q[S_TOK * EMB];
__device__ float g_k[S_TOK * EMB];

__device__ __align__(16) __nv_bfloat16 g_hs_hi[S_TOK * EMB];
__device__ __align__(16) __nv_bfloat16 g_hs_lo[S_TOK * EMB];
__device__ __align__(16) __nv_bfloat16 g_k_hi[S_TOK * EMB];
__device__ __align__(16) __nv_bfloat16 g_k_lo[S_TOK * EMB];
__device__ __align__(16) __nv_bfloat16 g_v_hi[S_TOK * EMB];   // reused: V fp16 (bitcast)
__device__ __align__(16) __nv_bfloat16 g_v_lo[S_TOK * EMB];   // reused: hs fp16 (bitcast)
__device__ __align__(16) __half       g_a_f16[S_TOK * EMB];
__device__ __align__(16) __nv_bfloat16 g_w_hi[4][EMB * EMB];  // [2]=vw fp16, [3]=ow fp16 (bitcast)
__device__ __align__(16) __nv_bfloat16 g_w_lo[4][EMB * EMB];

// ---------------- helpers ----------------------------------------------------
__device__ __forceinline__ uint32_t smem_u32(const void* p) {
    uint32_t a;
    asm("{ .reg .u64 t; cvta.to.shared.u64 t, %1; cvt.u32.u64 %0, t; }"
        : "=r"(a) : "l"(p));
    return a;
}

#define CP_ASYNC16(dst, src) \
    asm volatile("cp.async.cg.shared.global [%0], [%1], 16;" :: "r"(dst), "l"(src))
#define CP_COMMIT() asm volatile("cp.async.commit_group;" ::: "memory")
#define CP_WAIT(n)  asm volatile("cp.async.wait_group %0;" :: "n"(n) : "memory")

#define LDSM_X4(r, addr) \
    asm volatile("ldmatrix.sync.aligned.m8n8.x4.shared.b16 {%0,%1,%2,%3}, [%4];" \
        : "=r"((r)[0]), "=r"((r)[1]), "=r"((r)[2]), "=r"((r)[3]) : "r"(addr))
#define LDSM_X4_T(r, addr) \
    asm volatile("ldmatrix.sync.aligned.m8n8.x4.trans.shared.b16 {%0,%1,%2,%3}, [%4];" \
        : "=r"((r)[0]), "=r"((r)[1]), "=r"((r)[2]), "=r"((r)[3]) : "r"(addr))

#define MMA16816(d, a, b0, b1) \
    asm volatile("mma.sync.aligned.m16n8k16.row.col.f32.bf16.bf16.f32 " \
        "{%0,%1,%2,%3}, {%4,%5,%6,%7}, {%8,%9}, {%0,%1,%2,%3};" \
        : "+f"((d)[0]), "+f"((d)[1]), "+f"((d)[2]), "+f"((d)[3]) \
        : "r"((a)[0]), "r"((a)[1]), "r"((a)[2]), "r"((a)[3]), "r"(b0), "r"(b1))

#define MMA16816H(d, a, b0, b1) \
    asm volatile("mma.sync.aligned.m16n8k16.row.col.f32.f16.f16.f32 " \
        "{%0,%1,%2,%3}, {%4,%5,%6,%7}, {%8,%9}, {%0,%1,%2,%3};" \
        : "+f"((d)[0]), "+f"((d)[1]), "+f"((d)[2]), "+f"((d)[3]) \
        : "r"((a)[0]), "r"((a)[1]), "r"((a)[2]), "r"((a)[3]), "r"(b0), "r"(b1))

__device__ __forceinline__ uint32_t pk2(float lo, float hi) {
    uint32_t r;
    asm("cvt.rn.bf16x2.f32 %0, %1, %2;" : "=r"(r) : "f"(hi), "f"(lo));
    return r;
}
__device__ __forceinline__ uint32_t pk2h(float lo, float hi) {
    uint32_t r;
    asm("cvt.rn.f16x2.f32 %0, %1, %2;" : "=r"(r) : "f"(hi), "f"(lo));
    return r;
}
__device__ __forceinline__ float f2b(float x) {
    return __bfloat162float(__float2bfloat16(x));
}

// ---------------------------------------------------------------------------
// split-bf16 HMMA GEMM (verified): BM=BN=128, BK=32, 2-stage. fp32 out.
// ---------------------------------------------------------------------------
__device__ __forceinline__ void gemm_mma_tile(
    const __nv_bfloat16* __restrict__ Ahi, const __nv_bfloat16* __restrict__ Alo,
    const __nv_bfloat16* __restrict__ Whi, const __nv_bfloat16* __restrict__ Wlo,
    const float* __restrict__ bias, float* __restrict__ C)
{
    extern __shared__ __align__(16) char smem[];
    const uint32_t sbase = smem_u32(smem);

    const int tid  = threadIdx.x;
    const int lane = tid & 31;
    const int w    = tid >> 5;
    const int wm   = w & 1;
    const int wn   = w >> 1;
    const int rBase = blockIdx.y * 128;
    const int cBase = blockIdx.x * 128;

    const int j = lane >> 3;
    const int l8 = lane & 7;
    const uint32_t a_lane_off =
        (uint32_t)((wm * 64 + (j & 1) * 8 + l8) * TILE_STRIDE + ((j >> 1) * 8) * 2);
    const uint32_t b_lane_off = (uint32_t)(2 * TILE_BYTES +
        (wn * 32 + (j >> 1) * 8 + l8) * TILE_STRIDE + ((j & 1) * 8) * 2);

    float acc[4][4][4];
#pragma unroll
    for (int mt = 0; mt < 4; mt++)
#pragma unroll
        for (int nt = 0; nt < 4; nt++)
#pragma unroll
            for (int e = 0; e < 4; e++) acc[mt][nt][e] = 0.f;

    auto load_stage = [&](int s, int kc) {
        const uint32_t dst0 = sbase + s * STAGE_BYTES;
        const int row = tid >> 2;
        const int c   = tid & 3;
        const __nv_bfloat16* gsrc[4] = { Ahi, Alo, Whi, Wlo };
        const int gRow[4] = { rBase, rBase, cBase, cBase };
#pragma unroll
        for (int t = 0; t < 4; t++) {
#pragma unroll
            for (int half = 0; half < 2; half++) {
                const int r = row + half * 64;
                const __nv_bfloat16* src =
                    gsrc[t] + (size_t)(gRow[t] + r) * KDIM + kc + c * 8;
                const uint32_t dst = dst0 + t * TILE_BYTES + r * TILE_STRIDE + c * 16;
                CP_ASYNC16(dst, src);
            }
        }
    };

    load_stage(0, 0);
    CP_COMMIT();

    for (int i = 0; i < NCHUNK; i++) {
        if (i + 1 < NCHUNK) {
            load_stage((i + 1) & 1, (i + 1) * BK);
            CP_COMMIT();
            CP_WAIT(1);
        } else {
            CP_WAIT(0);
        }
        __syncthreads();

        const uint32_t base = sbase + (i & 1) * STAGE_BYTES;
#pragma unroll
        for (int ks = 0; ks < 2; ks++) {
            const uint32_t koff = ks * 32;
            uint32_t bh[2][4], bl[2][4];
#pragma unroll
            for (int p = 0; p < 2; p++) {
                const uint32_t bo = base + b_lane_off + p * (16 * TILE_STRIDE) + koff;
                LDSM_X4(bh[p], bo);
                LDSM_X4(bl[p], bo + TILE_BYTES);
            }
#pragma unroll
            for (int mt = 0; mt < 4; mt++) {
                uint32_t ah[4], al[4];
                const uint32_t ao = base + a_lane_off + mt * (16 * TILE_STRIDE) + koff;
                LDSM_X4(ah, ao);
                LDSM_X4(al, ao + TILE_BYTES);
#pragma unroll
                for (int nt = 0; nt < 4; nt++) {
                    const int p = nt >> 1, s2 = (nt & 1) * 2;
                    MMA16816(acc[mt][nt], ah, bh[p][s2], bh[p][s2 + 1]);
                    MMA16816(acc[mt][nt], al, bh[p][s2], bh[p][s2 + 1]);
                    MMA16816(acc[mt][nt], ah, bl[p][s2], bl[p][s2 + 1]);
                }
            }
        }
        __syncthreads();
    }

    const int qr = lane >> 2;
    const int qc = (lane & 3) * 2;
#pragma unroll
    for (int mt = 0; mt < 4; mt++) {
#pragma unroll
        for (int nt = 0; nt < 4; nt++) {
            const int row = rBase + wm * 64 + mt * 16 + qr;
            const int col = cBase + wn * 32 + nt * 8 + qc;
            const float b0 = bias[col], b1 = bias[col + 1];
            *(float2*)(C + (size_t)row * EMB + col) =
                make_float2(acc[mt][nt][0] + b0, acc[mt][nt][1] + b1);
            *(float2*)(C + (size_t)(row + 8) * EMB + col) =
                make_float2(acc[mt][nt][2] + b0, acc[mt][nt][3] + b1);
        }
    }
}

__global__ __launch_bounds__(256, 2) void qk_mma_kernel(
    const __nv_bfloat16* __restrict__ Ahi, const __nv_bfloat16* __restrict__ Alo,
    const __nv_bfloat16* __restrict__ whi, const __nv_bfloat16* __restrict__ wlo,
    const float* __restrict__ qb, const float* __restrict__ kb,
    float* __restrict__ Cq, float* __restrict__ Ck)
{
    const __nv_bfloat16* Bhi = whi + (size_t)blockIdx.z * EMB * EMB;
    const __nv_bfloat16* Blo = wlo + (size_t)blockIdx.z * EMB * EMB;
    if (blockIdx.z == 0)
        gemm_mma_tile(Ahi, Alo, Bhi, Blo, qb, Cq);
    else
        gemm_mma_tile(Ahi, Alo, Bhi, Blo, kb, Ck);
}

// ---------------------------------------------------------------------------
// fp16 1-term GEMM: BM=128, BN=64, BK=32, 3-stage. outMode 0: fp32; 1: fp16.
// ---------------------------------------------------------------------------
__device__ __forceinline__ void gemm_f16_tile(
    const __half* __restrict__ A, const __half* __restrict__ W,
    const float* __restrict__ bias, float* __restrict__ C,
    __half* __restrict__ C16, int outMode)
{
    extern __shared__ __align__(16) char smem[];
    const uint32_t sbase = smem_u32(smem);

    const int tid  = threadIdx.x;
    const int lane = tid & 31;
    const int w    = tid >> 5;
    const int wm   = w & 3;
    const int wn   = w >> 2;
    const int rBase = blockIdx.y * 128;
    const int cBase = blockIdx.x * 64;

    const int j  = lane >> 3;
    const int l8 = lane & 7;
    const uint32_t a_lane_off =
        (uint32_t)((wm * 32 + (j & 1) * 8 + l8) * 80 + (j >> 1) * 16);
    const uint32_t b_lane_off =
        (uint32_t)((wn * 32 + (j >> 1) * 8 + l8) * 80 + (j & 1) * 16);

    float acc[2][4][4];
#pragma unroll
    for (int mt = 0; mt < 2; mt++)
#pragma unroll
        for (int nt = 0; nt < 4; nt++)
#pragma unroll
            for (int e = 0; e < 4; e++) acc[mt][nt][e] = 0.f;

    auto load_stage = [&](int s, int kc) {
        const uint32_t dst0 = sbase + s * P_STAGE;
        {
            const int r = tid >> 1, c0 = (tid & 1) * 2;
            const size_t g = (size_t)(rBase + r) * KDIM + kc + c0 * 8;
            const uint32_t d = dst0 + P_A + r * 80 + c0 * 16;
            CP_ASYNC16(d,      A + g);
            CP_ASYNC16(d + 16, A + g + 8);
        }
        {
            const int r = tid >> 2, c = tid & 3;
            const size_t g = (size_t)(cBase + r) * KDIM + kc + c * 8;
            CP_ASYNC16(dst0 + P_B + r * 80 + c * 16, W + g);
        }
    };

    load_stage(0, 0); CP_COMMIT();
    load_stage(1, BK); CP_COMMIT();

    for (int i = 0; i < NCHUNK; i++) {
        if (i + 1 < NCHUNK) { CP_WAIT(1); } else { CP_WAIT(0); }
        __syncthreads();
        if (i + 2 < NCHUNK) {
            load_stage((i + 2) % 3, (i + 2) * BK);
            CP_COMMIT();
        }

        const uint32_t base = sbase + (i % 3) * P_STAGE;
#pragma unroll
        for (int ks = 0; ks < 2; ks++) {
            const uint32_t koff = ks * 32;
            uint32_t bh[2][4];
#pragma unroll
            for (int p = 0; p < 2; p++)
                LDSM_X4(bh[p], base + P_B + b_lane_off + p * 1280 + koff);
#pragma unroll
            for (int mt = 0; mt < 2; mt++) {
                uint32_t ah[4];
                LDSM_X4(ah, base + P_A + a_lane_off + mt * 1280 + koff);
#pragma unroll
                for (int nt = 0; nt < 4; nt++) {
                    const int p = nt >> 1, s2 = (nt & 1) * 2;
                    MMA16816H(acc[mt][nt], ah, bh[p][s2], bh[p][s2 + 1]);
                }
            }
        }
    }

    const int qr = lane >> 2;
    const int qc = (lane & 3) * 2;
#pragma unroll
    for (int mt = 0; mt < 2; mt++) {
#pragma unroll
        for (int nt = 0; nt < 4; nt++) {
            const int row = rBase + wm * 32 + mt * 16 + qr;
            const int col = cBase + wn * 32 + nt * 8 + qc;
            const float b0 = bias[col], b1 = bias[col + 1];
            float v00 = acc[mt][nt][0] + b0, v01 = acc[mt][nt][1] + b1;
            float v10 = acc[mt][nt][2] + b0, v11 = acc[mt][nt][3] + b1;
            if (outMode == 0) {
                *(float2*)(C + (size_t)row * EMB + col) = make_float2(v00, v01);
                *(float2*)(C + (size_t)(row + 8) * EMB + col) = make_float2(v10, v11);
            } else {
                *(uint32_t*)(C16 + (size_t)row * EMB + col) = pk2h(v00, v01);
                *(uint32_t*)(C16 + (size_t)(row + 8) * EMB + col) = pk2h(v10, v11);
            }
        }
    }
}

__global__ __launch_bounds__(256, 2) void oproj_f16_kernel(
    const __half* __restrict__ A, const __half* __restrict__ W,
    const float* __restrict__ bias, float* __restrict__ C)
{
    gemm_f16_tile(A, W, bias, C, nullptr, 0);
}

__global__ __launch_bounds__(256, 2) void vproj_f16_kernel(
    const __half* __restrict__ A, const __half* __restrict__ W,
    const float* __restrict__ bias, __half* __restrict__ C16)
{
    gemm_f16_tile(A, W, bias, nullptr, C16, 1);
}

// ---------------- batched conversions ----------------------------------------
// hs -> bf16 hi/lo + fp16; qw/kw -> bf16 hi/lo; vw/ow -> fp16.
#define HS8 (S_TOK * EMB / 8)
#define W8  (EMB * EMB / 8)
#define CVT_TOTAL (HS8 + 4 * W8)

__global__ __launch_bounds__(256) void cvt_all_kernel(
    const float* __restrict__ hs, const float* __restrict__ qw,
    const float* __restrict__ kw, const float* __restrict__ vw,
    const float* __restrict__ ow,
    __nv_bfloat16* __restrict__ hshi, __nv_bfloat16* __restrict__ hslo,
    __half* __restrict__ hs16,
    __nv_bfloat16* __restrict__ whi, __nv_bfloat16* __restrict__ wlo)
{
    int t = blockIdx.x * blockDim.x + threadIdx.x;
    if (t >= CVT_TOTAL) return;
    const float* src;
    __nv_bfloat16 *hi, *lo;
    size_t off;
    int wsel = -1;
    if (t < HS8) {
        src = hs; hi = hshi; lo = hslo; off = (size_t)t * 8;
    } else {
        int r = t - HS8;
        wsel = r / W8;
        int loc = r - wsel * W8;
        const float* ws[4] = { qw, kw, vw, ow };
        src = ws[wsel];
        hi = whi + (size_t)wsel * EMB * EMB;
        lo = wlo + (size_t)wsel * EMB * EMB;
        off = (size_t)loc * 8;
    }
    const float4* s4 = (const float4*)(src + off);
    float4 a = s4[0], b = s4[1];
    float v[8] = {a.x, a.y, a.z, a.w, b.x, b.y, b.z, b.w};
    if (wsel >= 2) {
        // vw / ow -> fp16 single, stored in whi[wsel] (bit-cast)
        uint32_t p[4];
#pragma unroll
        for (int k = 0; k < 4; k++) p[k] = pk2h(v[2 * k], v[2 * k + 1]);
        *(uint4*)(hi + off) = make_uint4(p[0], p[1], p[2], p[3]);
    } else {
        __nv_bfloat16 h[8], l[8];
#pragma unroll
        for (int k = 0; k < 8; k++) {
            h[k] = __float2bfloat16(v[k]);
            l[k] = __float2bfloat16(v[k] - __bfloat162float(h[k]));
        }
        *(uint4*)(hi + off) = *(uint4*)h;
        *(uint4*)(lo + off) = *(uint4*)l;
        if (wsel < 0) {
            uint32_t p[4];
#pragma unroll
            for (int k = 0; k < 4; k++) p[k] = pk2h(v[2 * k], v[2 * k + 1]);
            *(uint4*)(hs16 + off) = make_uint4(p[0], p[1], p[2], p[3]);
        }
    }
}

// ---------------- prep: RoPE + (scale) + split Q and K ----------------------
__global__ __launch_bounds__(256) void prep_qk_kernel(
    const float* __restrict__ Q, const float* __restrict__ K,
    __nv_bfloat16* __restrict__ qh, __nv_bfloat16* __restrict__ ql,
    __nv_bfloat16* __restrict__ kh, __nv_bfloat16* __restrict__ kl,
    const float* __restrict__ cosp, const float* __restrict__ sinp)
{
    int idx = blockIdx.x * blockDim.x + threadIdx.x;
    if (idx >= S_TOK * NH * 9) return;
    const int c = idx % 9;
    const int t = idx / 9;
    const int h = t % NH;
    const int s = t / NH;
    const size_t gb = (size_t)s * EMB + h * HD + c * 4;
    const size_t pb = (size_t)s * HD + c * 4;
    const float scale = rsqrtf((float)HD);

    float4 cl = *(const float4*)(cosp + pb);
    float4 sl = *(const float4*)(sinp + pb);
    float4 ch = *(const float4*)(cosp + pb + 36);
    float4 sh = *(const float4*)(sinp + pb + 36);

    {   // Q (scaled)
        float4 a = *(const float4*)(Q + gb);
        float4 b = *(const float4*)(Q + gb + 36);
        float lo4[4] = { (a.x * cl.x - b.x * sl.x) * scale, (a.y * cl.y - b.y * sl.y) * scale,
                         (a.z * cl.z - b.z * sl.z) * scale, (a.w * cl.w - b.w * sl.w) * scale };
        float hi4[4] = { (b.x * ch.x + a.x * sh.x) * scale, (b.y * ch.y + a.y * sh.y) * scale,
                         (b.z * ch.z + a.z * sh.z) * scale, (b.w * ch.w + a.w * sh.w) * scale };
        float lr[4], hr[4];
#pragma unroll
        for (int e = 0; e < 4; e++) { lr[e] = lo4[e] - f2b(lo4[e]); hr[e] = hi4[e] - f2b(hi4[e]); }
        *(uint2*)(qh + gb)      = make_uint2(pk2(lo4[0], lo4[1]), pk2(lo4[2], lo4[3]));
        *(uint2*)(qh + gb + 36) = make_uint2(pk2(hi4[0], hi4[1]), pk2(hi4[2], hi4[3]));
        *(uint2*)(ql + gb)      = make_uint2(pk2(lr[0], lr[1]), pk2(lr[2], lr[3]));
        *(uint2*)(ql + gb + 36) = make_uint2(pk2(hr[0], hr[1]), pk2(hr[2], hr[3]));
    }
    {   // K (unscaled)
        float4 a = *(const float4*)(K + gb);
        float4 b = *(const float4*)(K + gb + 36);
        float lo4[4] = { a.x * cl.x - b.x * sl.x, a.y * cl.y - b.y * sl.y,
                         a.z * cl.z - b.z * sl.z, a.w * cl.w - b.w * sl.w };
        float hi4[4] = { b.x * ch.x + a.x * sh.x, b.y * ch.y + a.y * sh.y,
                         b.z * ch.z + a.z * sh.z, b.w * ch.w + a.w * sh.w };
        float lr[4], hr[4];
#pragma unroll
        for (int e = 0; e < 4; e++) { lr[e] = lo4[e] - f2b(lo4[e]); hr[e] = hi4[e] - f2b(hi4[e]); }
        *(uint2*)(kh + gb)      = make_uint2(pk2(lo4[0], lo4[1]), pk2(lo4[2], lo4[3]));
        *(uint2*)(kh + gb + 36) = make_uint2(pk2(hi4[0], hi4[1]), pk2(hi4[2], hi4[3]));
        *(uint2*)(kl + gb)      = make_uint2(pk2(lr[0], lr[1]), pk2(lr[2], lr[3]));
        *(uint2*)(kl + gb + 36) = make_uint2(pk2(hr[0], hr[1]), pk2(hr[2], hr[3]));
    }
}

// ---------------------------------------------------------------------------
// HMMA flash attention: QK bf16 3-term, PV fp16 1-term, fp16 output.
// ---------------------------------------------------------------------------
__global__ __launch_bounds__(256, 2) void attn_mma_kernel(
    const __nv_bfloat16* __restrict__ QH, const __nv_bfloat16* __restrict__ QL,
    const __nv_bfloat16* __restrict__ KHg, const __nv_bfloat16* __restrict__ KLg,
    const __half* __restrict__ V16g,
    __half* __restrict__ O16,
    const int* __restrict__ cu, int nseg)
{
    extern __shared__ __align__(16) char asmem[];
    const uint32_t sb = smem_u32(asmem);

    const int tid  = threadIdx.x;
    const int lane = tid & 31;
    const int w    = tid >> 5;
    const int h    = blockIdx.y;
    const int q0   = blockIdx.x * 128;

    int segStart = 0, segEnd = S_TOK;
    for (int i = 0; i < nseg; i++) {
        int a = cu[i], b = cu[i + 1];
        if (q0 >= a && q0 < b) { segStart = a; segEnd = b; }
    }
    const int ntiles = (segEnd - segStart + 31) / 32;

    // zero pad bytes (dims 72..79): Q rows + all 3 KV stage buffers (K hi/lo, V)
    for (int i = tid; i < 128; i += 256) {
        *(uint4*)(asmem + AQ_H + i * A_ROWB + 144) = make_uint4(0, 0, 0, 0);
        *(uint4*)(asmem + AQ_L + i * A_ROWB + 144) = make_uint4(0, 0, 0, 0);
    }
    for (int i = tid; i < 3 * 32; i += 256) {
        const int b = i / 32, r = i % 32;
        char* rowp = asmem + AKV0 + b * KVS + r * A_ROWB + 144;
        *(uint4*)(rowp + KO_H) = make_uint4(0, 0, 0, 0);
        *(uint4*)(rowp + KO_L) = make_uint4(0, 0, 0, 0);
        *(uint4*)(rowp + VO)   = make_uint4(0, 0, 0, 0);
    }

    for (int i = tid; i < 128 * 9; i += 256) {
        const int r = i / 9, c = i % 9;
        const size_t g = (size_t)(q0 + r) * EMB + h * HD + c * 8;
        CP_ASYNC16(sb + AQ_H + r * A_ROWB + c * 16, QH + g);
        CP_ASYNC16(sb + AQ_L + r * A_ROWB + c * 16, QL + g);
    }
    CP_COMMIT();

    auto stage_kv = [&](int tt) {
        const int b = tt % 3;
        const int kt = segStart + tt * 32;
        const uint32_t dst0 = sb + AKV0 + b * KVS;
        for (int i = tid; i < 32 * 9; i += 256) {
            const int r = i / 9, c = i % 9;
            const int key = kt + r;
            if (key < segEnd) {
                const size_t g = (size_t)key * EMB + h * HD + c * 8;
                const uint32_t d = dst0 + r * A_ROWB + c * 16;
                CP_ASYNC16(d + KO_H, KHg + g);
                CP_ASYNC16(d + KO_L, KLg + g);
                CP_ASYNC16(d + VO,   V16g + g);
            }
        }
    };

    stage_kv(0); CP_COMMIT();
    if (ntiles > 1) { stage_kv(1); CP_COMMIT(); }

    const int j  = lane >> 3;
    const int l8 = lane & 7;
    const uint32_t q_off  = (uint32_t)((16 * w + (j & 1) * 8 + l8) * A_ROWB + (j >> 1) * 16);
    const uint32_t bs_off = (uint32_t)(((j >> 1) * 8 + l8) * A_ROWB + (j & 1) * 16);
    const uint32_t v_off  = (uint32_t)(((j & 1) * 8 + l8) * A_ROWB + (j >> 1) * 16);

    const int qr = lane >> 2;
    const int lc = lane & 3;

    float acc_o[10][4];
#pragma unroll
    for (int dt = 0; dt < 10; dt++)
#pragma unroll
        for (int e = 0; e < 4; e++) acc_o[dt][e] = 0.f;
    float lsum0 = 0.f, lsum1 = 0.f;

    for (int tt = 0; tt < ntiles; tt++) {
        const int kt = segStart + tt * 32;
        if (tt + 1 < ntiles) { CP_WAIT(1); } else { CP_WAIT(0); }
        __syncthreads();
        if (tt + 2 < ntiles) { stage_kv(tt + 2); CP_COMMIT(); }

        const uint32_t kvb = sb + AKV0 + (tt % 3) * KVS;

        if (kt + 32 > segEnd) {
            for (int i = tid; i < 32 * 9; i += 256) {
                const int r = i / 9, c = i % 9;
                if (kt + r >= segEnd) {
                    char* dp2 = asmem + (kvb - sb) + r * A_ROWB + c * 16;
                    *(uint4*)(dp2 + KO_H) = make_uint4(0, 0, 0, 0);
                    *(uint4*)(dp2 + KO_L) = make_uint4(0, 0, 0, 0);
                    *(uint4*)(dp2 + VO)   = make_uint4(0, 0, 0, 0);
                }
            }
            __syncthreads();
        }

        // ---- S = Q K^T (bf16 3-term), 32 keys -----------------------------
        float acc_s[4][4];
#pragma unroll
        for (int nt = 0; nt < 4; nt++)
#pragma unroll
            for (int e = 0; e < 4; e++) acc_s[nt][e] = 0.f;

#pragma unroll
        for (int kc = 0; kc < 5; kc++) {
            uint32_t qh[4], ql[4];
            const uint32_t ao = sb + AQ_H + q_off + kc * 32;
            LDSM_X4(qh, ao);
            LDSM_X4(ql, ao + (AQ_L - AQ_H));
#pragma unroll
            for (int np = 0; np < 2; np++) {
                uint32_t bh[4], bl[4];
                const uint32_t bo = kvb + KO_H + bs_off + np * (16 * A_ROWB) + kc * 32;
                LDSM_X4(bh, bo);
                LDSM_X4(bl, bo + (KO_L - KO_H));
                MMA16816(acc_s[2 * np],     qh, bh[0], bh[1]);
                MMA16816(acc_s[2 * np],     ql, bh[0], bh[1]);
                MMA16816(acc_s[2 * np],     qh, bl[0], bl[1]);
                MMA16816(acc_s[2 * np + 1], qh, bh[2], bh[3]);
                MMA16816(acc_s[2 * np + 1], ql, bh[2], bh[3]);
                MMA16816(acc_s[2 * np + 1], qh, bl[2], bl[3]);
            }
        }

        // ---- softmax (unnormalized) + mask --------------------------------
#pragma unroll
        for (int nt = 0; nt < 4; nt++) {
            const int colb = kt + nt * 8 + lc * 2;
            float p0 = (colb     < segEnd) ? __expf(acc_s[nt][0]) : 0.f;
            float p1 = (colb + 1 < segEnd) ? __expf(acc_s[nt][1]) : 0.f;
            float p2 = (colb     < segEnd) ? __expf(acc_s[nt][2]) : 0.f;
            float p3 = (colb + 1 < segEnd) ? __expf(acc_s[nt][3]) : 0.f;
            lsum0 += p0 + p1;
            lsum1 += p2 + p3;
            acc_s[nt][0] = p0; acc_s[nt][1] = p1;
            acc_s[nt][2] = p2; acc_s[nt][3] = p3;
        }

        // ---- O += P V (fp16 1-term) ---------------------------------------
#pragma unroll
        for (int kc = 0; kc < 2; kc++) {
            uint32_t pa[4];
            const float* s0 = acc_s[2 * kc];
            const float* s1 = acc_s[2 * kc + 1];
            pa[0] = pk2h(s0[0], s0[1]); pa[1] = pk2h(s0[2], s0[3]);
            pa[2] = pk2h(s1[0], s1[1]); pa[3] = pk2h(s1[2], s1[3]);
#pragma unroll
            for (int dp = 0; dp < 5; dp++) {
                uint32_t vh[4];
                const uint32_t vo = kvb + VO + v_off + kc * (16 * A_ROWB) + dp * 32;
                LDSM_X4_T(vh, vo);
                MMA16816H(acc_o[2 * dp],     pa, vh[0], vh[1]);
                MMA16816H(acc_o[2 * dp + 1], pa, vh[2], vh[3]);
            }
        }
    }

    // ---- epilogue: normalize, write fp16 ----------------------------------
    lsum0 += __shfl_xor_sync(0xffffffffu, lsum0, 1);
    lsum0 += __shfl_xor_sync(0xffffffffu, lsum0, 2);
    lsum1 += __shfl_xor_sync(0xffffffffu, lsum1, 1);
    lsum1 += __shfl_xor_sync(0xffffffffu, lsum1, 2);
    const float inv0 = 1.0f / lsum0;
    const float inv1 = 1.0f / lsum1;
    const int row0 = q0 + 16 * w + qr;
    const int row1 = row0 + 8;
#pragma unroll
    for (int dt = 0; dt < 9; dt++) {
        const int d = dt * 8 + lc * 2;
        *(uint32_t*)(O16 + (size_t)row0 * EMB + h * HD + d) =
            pk2h(acc_o[dt][0] * inv0, acc_o[dt][1] * inv0);
        *(uint32_t*)(O16 + (size_t)row1 * EMB + h * HD + d) =
            pk2h(acc_o[dt][2] * inv1, acc_o[dt][3] * inv1);
    }
}

// ---------------------------------------------------------------------------
extern "C" void kernel_launch(void* const* d_in, const int* in_sizes, int n_in,
                              void* d_out, int out_size)
{
    const float* hs   = (const float*)d_in[0];
    const float* qw   = (const float*)d_in[1];
    const float* qb   = (const float*)d_in[2];
    const float* kw   = (const float*)d_in[3];
    const float* kb   = (const float*)d_in[4];
    const float* vw   = (const float*)d_in[5];
    const float* vb   = (const float*)d_in[6];
    const float* ow   = (const float*)d_in[7];
    const float* ob   = (const float*)d_in[8];
    const float* cosp = (const float*)d_in[9];
    const float* sinp = (const float*)d_in[10];
    const int*   cu   = (const int*)d_in[11];
    const int nseg = in_sizes[11] - 1;

    float *qp, *kp;
    cudaGetSymbolAddress((void**)&qp, g_q);
    cudaGetSymbolAddress((void**)&kp, g_k);
    __nv_bfloat16 *hshi, *hslo, *khi, *klo, *whi, *wlo;
    __nv_bfloat16 *vhi_raw, *vlo_raw;
    __half *a16;
    cudaGetSymbolAddress((void**)&hshi, g_hs_hi);
    cudaGetSymbolAddress((void**)&hslo, g_hs_lo);
    cudaGetSymbolAddress((void**)&khi, g_k_hi);
    cudaGetSymbolAddress((void**)&klo, g_k_lo);
    cudaGetSymbolAddress((void**)&vhi_raw, g_v_hi);
    cudaGetSymbolAddress((void**)&vlo_raw, g_v_lo);
    cudaGetSymbolAddress((void**)&a16, g_a_f16);
    cudaGetSymbolAddress((void**)&whi, g_w_hi);
    cudaGetSymbolAddress((void**)&wlo, g_w_lo);
    __half* v16  = (__half*)vhi_raw;   // V fp16 output of vproj
    __half* hs16 = (__half*)vlo_raw;   // hs fp16 input of vproj

    cudaFuncSetAttribute(qk_mma_kernel,
                         cudaFuncAttributeMaxDynamicSharedMemorySize, GEMM_SMEM);
    cudaFuncSetAttribute(oproj_f16_kernel,
                         cudaFuncAttributeMaxDynamicSharedMemorySize, OPJ_SMEM);
    cudaFuncSetAttribute(vproj_f16_kernel,
                         cudaFuncAttributeMaxDynamicSharedMemorySize, OPJ_SMEM);
    cudaFuncSetAttribute(attn_mma_kernel,
                         cudaFuncAttributeMaxDynamicSharedMemorySize, ATTN_SMEM);

    // 0) conversions
    cvt_all_kernel<<<(CVT_TOTAL + 255) / 256, 256>>>(
        hs, qw, kw, vw, ow, hshi, hslo, hs16, whi, wlo);

    // 1a) Q/K projections (bf16 3-term)
    qk_mma_kernel<<<dim3(EMB / 128, S_TOK / 128, 2), 256, GEMM_SMEM>>>(
        hshi, hslo, whi, wlo, qb, kb, qp, kp);

    // 1b) V projection (fp16 1-term) -> v16
    vproj_f16_kernel<<<dim3(EMB / 64, S_TOK / 128), 256, OPJ_SMEM>>>(
        hs16, (const __half*)(whi + 2 * (size_t)EMB * EMB), vb, v16);

    // 2) prep: RoPE + scale + split Q/K
    prep_qk_kernel<<<(S_TOK * NH * 9 + 255) / 256, 256>>>(
        qp, kp, hshi, hslo, khi, klo, cosp, sinp);

    // 3) attention (QK bf16 3-term, PV fp16 1-term) -> a16
    attn_mma_kernel<<<dim3(S_TOK / 128, NH), 256, ATTN_SMEM>>>(
        hshi, hslo, khi, klo, v16, a16, cu, nseg);

    // 4) O projection (fp16 1-term) -> d_out
    oproj_f16_kernel<<<dim3(EMB / 64, S_TOK / 128), 256, OPJ_SMEM>>>(
        a16, (const __half*)(whi + 3 * (size_t)EMB * EMB), ob, (float*)d_out);
}

// round 12
// speedup vs baseline: 2.1102x; 1.4267x over previous
#include <cuda_runtime.h>
#include <cuda_bf16.h>
#include <cuda_fp16.h>
#include <cstdint>
#include <math.h>

#define S_TOK 2048
#define EMB   1152
#define NH    16
#define HD    72
#define KDIM  1152
#define BK    32
#define NCHUNK (KDIM / BK)          // 36

// ---- fp16 1-term GEMM (qkv / oproj): BM=128, BN=64, 3-stage ----
#define P_A 0
#define P_B 10240
#define P_STAGE 15360
#define PRJ_SMEM (3 * P_STAGE)      // 46080

// ---- attention smem: Q fp16 hi/lo + 3 KV stages (K fp16, V fp16) ----
#define A_ROWB 176
#define AQ_H 0
#define AQ_L 22528
#define AKV0 45056
#define KO   0
#define VO   5632
#define KVS  11264
#define ATTN_SMEM (45056 + 3 * KVS)   // 78848

// ---------------- scratch ----------------------------------------------------
__device__ float g_q[S_TOK * EMB];
__device__ float g_k[S_TOK * EMB];

__device__ __align__(16) __half g_q_hi[S_TOK * EMB];   // Q fp16 hi (prep out)
__device__ __align__(16) __half g_q_lo[S_TOK * EMB];   // Q fp16 lo
__device__ __align__(16) __half g_k_16[S_TOK * EMB];   // K fp16 (prep out)
__device__ __align__(16) __half g_v_16[S_TOK * EMB];   // V fp16 (vproj out)
__device__ __align__(16) __half g_hs16[S_TOK * EMB];   // hs fp16
__device__ __align__(16) __half g_a16 [S_TOK * EMB];   // attention out fp16
__device__ __align__(16) __half g_w16 [4][EMB * EMB];  // qw/kw/vw/ow fp16

// ---------------- helpers ----------------------------------------------------
__device__ __forceinline__ uint32_t smem_u32(const void* p) {
    uint32_t a;
    asm("{ .reg .u64 t; cvta.to.shared.u64 t, %1; cvt.u32.u64 %0, t; }"
        : "=r"(a) : "l"(p));
    return a;
}

#define CP_ASYNC16(dst, src) \
    asm volatile("cp.async.cg.shared.global [%0], [%1], 16;" :: "r"(dst), "l"(src))
#define CP_COMMIT() asm volatile("cp.async.commit_group;" ::: "memory")
#define CP_WAIT(n)  asm volatile("cp.async.wait_group %0;" :: "n"(n) : "memory")

#define LDSM_X4(r, addr) \
    asm volatile("ldmatrix.sync.aligned.m8n8.x4.shared.b16 {%0,%1,%2,%3}, [%4];" \
        : "=r"((r)[0]), "=r"((r)[1]), "=r"((r)[2]), "=r"((r)[3]) : "r"(addr))
#define LDSM_X4_T(r, addr) \
    asm volatile("ldmatrix.sync.aligned.m8n8.x4.trans.shared.b16 {%0,%1,%2,%3}, [%4];" \
        : "=r"((r)[0]), "=r"((r)[1]), "=r"((r)[2]), "=r"((r)[3]) : "r"(addr))

#define MMA16816H(d, a, b0, b1) \
    asm volatile("mma.sync.aligned.m16n8k16.row.col.f32.f16.f16.f32 " \
        "{%0,%1,%2,%3}, {%4,%5,%6,%7}, {%8,%9}, {%0,%1,%2,%3};" \
        : "+f"((d)[0]), "+f"((d)[1]), "+f"((d)[2]), "+f"((d)[3]) \
        : "r"((a)[0]), "r"((a)[1]), "r"((a)[2]), "r"((a)[3]), "r"(b0), "r"(b1))

__device__ __forceinline__ uint32_t pk2h(float lo, float hi) {
    uint32_t r;
    asm("cvt.rn.f16x2.f32 %0, %1, %2;" : "=r"(r) : "f"(hi), "f"(lo));
    return r;
}
__device__ __forceinline__ float f2h(float x) {
    return __half2float(__float2half(x));
}

// ---------------------------------------------------------------------------
// fp16 1-term GEMM: BM=128, BN=64, BK=32, 3-stage. outMode 0: fp32; 1: fp16.
// (oproj config, measured ~20us @288 CTAs.)
// ---------------------------------------------------------------------------
__device__ __forceinline__ void gemm_f16_tile(
    const __half* __restrict__ A, const __half* __restrict__ W,
    const float* __restrict__ bias, float* __restrict__ C,
    __half* __restrict__ C16, int outMode)
{
    extern __shared__ __align__(16) char smem[];
    const uint32_t sbase = smem_u32(smem);

    const int tid  = threadIdx.x;
    const int lane = tid & 31;
    const int w    = tid >> 5;
    const int wm   = w & 3;
    const int wn   = w >> 2;
    const int rBase = blockIdx.y * 128;
    const int cBase = blockIdx.x * 64;

    const int j  = lane >> 3;
    const int l8 = lane & 7;
    const uint32_t a_lane_off =
        (uint32_t)((wm * 32 + (j & 1) * 8 + l8) * 80 + (j >> 1) * 16);
    const uint32_t b_lane_off =
        (uint32_t)((wn * 32 + (j >> 1) * 8 + l8) * 80 + (j & 1) * 16);

    float acc[2][4][4];
#pragma unroll
    for (int mt = 0; mt < 2; mt++)
#pragma unroll
        for (int nt = 0; nt < 4; nt++)
#pragma unroll
            for (int e = 0; e < 4; e++) acc[mt][nt][e] = 0.f;

    auto load_stage = [&](int s, int kc) {
        const uint32_t dst0 = sbase + s * P_STAGE;
        {
            const int r = tid >> 1, c0 = (tid & 1) * 2;
            const size_t g = (size_t)(rBase + r) * KDIM + kc + c0 * 8;
            const uint32_t d = dst0 + P_A + r * 80 + c0 * 16;
            CP_ASYNC16(d,      A + g);
            CP_ASYNC16(d + 16, A + g + 8);
        }
        {
            const int r = tid >> 2, c = tid & 3;
            const size_t g = (size_t)(cBase + r) * KDIM + kc + c * 8;
            CP_ASYNC16(dst0 + P_B + r * 80 + c * 16, W + g);
        }
    };

    load_stage(0, 0); CP_COMMIT();
    load_stage(1, BK); CP_COMMIT();

    for (int i = 0; i < NCHUNK; i++) {
        if (i + 1 < NCHUNK) { CP_WAIT(1); } else { CP_WAIT(0); }
        __syncthreads();
        if (i + 2 < NCHUNK) {
            load_stage((i + 2) % 3, (i + 2) * BK);
            CP_COMMIT();
        }

        const uint32_t base = sbase + (i % 3) * P_STAGE;
#pragma unroll
        for (int ks = 0; ks < 2; ks++) {
            const uint32_t koff = ks * 32;
            uint32_t bh[2][4];
#pragma unroll
            for (int p = 0; p < 2; p++)
                LDSM_X4(bh[p], base + P_B + b_lane_off + p * 1280 + koff);
#pragma unroll
            for (int mt = 0; mt < 2; mt++) {
                uint32_t ah[4];
                LDSM_X4(ah, base + P_A + a_lane_off + mt * 1280 + koff);
#pragma unroll
                for (int nt = 0; nt < 4; nt++) {
                    const int p = nt >> 1, s2 = (nt & 1) * 2;
                    MMA16816H(acc[mt][nt], ah, bh[p][s2], bh[p][s2 + 1]);
                }
            }
        }
    }

    const int qr = lane >> 2;
    const int qc = (lane & 3) * 2;
#pragma unroll
    for (int mt = 0; mt < 2; mt++) {
#pragma unroll
        for (int nt = 0; nt < 4; nt++) {
            const int row = rBase + wm * 32 + mt * 16 + qr;
            const int col = cBase + wn * 32 + nt * 8 + qc;
            const float b0 = bias[col], b1 = bias[col + 1];
            float v00 = acc[mt][nt][0] + b0, v01 = acc[mt][nt][1] + b1;
            float v10 = acc[mt][nt][2] + b0, v11 = acc[mt][nt][3] + b1;
            if (outMode == 0) {
                *(float2*)(C + (size_t)row * EMB + col) = make_float2(v00, v01);
                *(float2*)(C + (size_t)(row + 8) * EMB + col) = make_float2(v10, v11);
            } else {
                *(uint32_t*)(C16 + (size_t)row * EMB + col) = pk2h(v00, v01);
                *(uint32_t*)(C16 + (size_t)(row + 8) * EMB + col) = pk2h(v10, v11);
            }
        }
    }
}

// Q/K/V projections in one launch: z selects weight/bias/output.
__global__ __launch_bounds__(256, 2) void qkv_f16_kernel(
    const __half* __restrict__ hs16, const __half* __restrict__ w16,
    const float* __restrict__ qb, const float* __restrict__ kb,
    const float* __restrict__ vb,
    float* __restrict__ Cq, float* __restrict__ Ck, __half* __restrict__ V16)
{
    const __half* W = w16 + (size_t)blockIdx.z * EMB * EMB;
    if (blockIdx.z == 0)
        gemm_f16_tile(hs16, W, qb, Cq, nullptr, 0);
    else if (blockIdx.z == 1)
        gemm_f16_tile(hs16, W, kb, Ck, nullptr, 0);
    else
        gemm_f16_tile(hs16, W, vb, nullptr, V16, 1);
}

__global__ __launch_bounds__(256, 2) void oproj_f16_kernel(
    const __half* __restrict__ A, const __half* __restrict__ W,
    const float* __restrict__ bias, float* __restrict__ C)
{
    gemm_f16_tile(A, W, bias, C, nullptr, 0);
}

// ---------------- batched fp32 -> fp16 conversions ---------------------------
#define HS8 (S_TOK * EMB / 8)
#define W8  (EMB * EMB / 8)
#define CVT_TOTAL (HS8 + 4 * W8)

__global__ __launch_bounds__(256) void cvt_all_kernel(
    const float* __restrict__ hs, const float* __restrict__ qw,
    const float* __restrict__ kw, const float* __restrict__ vw,
    const float* __restrict__ ow,
    __half* __restrict__ hs16, __half* __restrict__ w16)
{
    int t = blockIdx.x * blockDim.x + threadIdx.x;
    if (t >= CVT_TOTAL) return;
    const float* src;
    __half* dst;
    size_t off;
    if (t < HS8) {
        src = hs; dst = hs16; off = (size_t)t * 8;
    } else {
        int r = t - HS8;
        int wsel = r / W8;
        int loc = r - wsel * W8;
        const float* ws[4] = { qw, kw, vw, ow };
        src = ws[wsel];
        dst = w16 + (size_t)wsel * EMB * EMB;
        off = (size_t)loc * 8;
    }
    const float4* s4 = (const float4*)(src + off);
    float4 a = s4[0], b = s4[1];
    float v[8] = {a.x, a.y, a.z, a.w, b.x, b.y, b.z, b.w};
    uint32_t p[4];
#pragma unroll
    for (int k = 0; k < 4; k++) p[k] = pk2h(v[2 * k], v[2 * k + 1]);
    *(uint4*)(dst + off) = make_uint4(p[0], p[1], p[2], p[3]);
}

// ---------------- prep: RoPE + (scale) -> fp16 (Q split hi/lo, K single) ----
__global__ __launch_bounds__(256) void prep_qk_kernel(
    const float* __restrict__ Q, const float* __restrict__ K,
    __half* __restrict__ qh, __half* __restrict__ ql,
    __half* __restrict__ k16,
    const float* __restrict__ cosp, const float* __restrict__ sinp)
{
    int idx = blockIdx.x * blockDim.x + threadIdx.x;
    if (idx >= S_TOK * NH * 9) return;
    const int c = idx % 9;
    const int t = idx / 9;
    const int h = t % NH;
    const int s = t / NH;
    const size_t gb = (size_t)s * EMB + h * HD + c * 4;
    const size_t pb = (size_t)s * HD + c * 4;
    const float scale = rsqrtf((float)HD);

    float4 cl = *(const float4*)(cosp + pb);
    float4 sl = *(const float4*)(sinp + pb);
    float4 ch = *(const float4*)(cosp + pb + 36);
    float4 sh = *(const float4*)(sinp + pb + 36);

    {   // Q (scaled), fp16 hi + lo residual
        float4 a = *(const float4*)(Q + gb);
        float4 b = *(const float4*)(Q + gb + 36);
        float rl[4] = { (a.x * cl.x - b.x * sl.x) * scale, (a.y * cl.y - b.y * sl.y) * scale,
                        (a.z * cl.z - b.z * sl.z) * scale, (a.w * cl.w - b.w * sl.w) * scale };
        float rh[4] = { (b.x * ch.x + a.x * sh.x) * scale, (b.y * ch.y + a.y * sh.y) * scale,
                        (b.z * ch.z + a.z * sh.z) * scale, (b.w * ch.w + a.w * sh.w) * scale };
        float el[4], eh[4];
#pragma unroll
        for (int e = 0; e < 4; e++) { el[e] = rl[e] - f2h(rl[e]); eh[e] = rh[e] - f2h(rh[e]); }
        *(uint2*)(qh + gb)      = make_uint2(pk2h(rl[0], rl[1]), pk2h(rl[2], rl[3]));
        *(uint2*)(qh + gb + 36) = make_uint2(pk2h(rh[0], rh[1]), pk2h(rh[2], rh[3]));
        *(uint2*)(ql + gb)      = make_uint2(pk2h(el[0], el[1]), pk2h(el[2], el[3]));
        *(uint2*)(ql + gb + 36) = make_uint2(pk2h(eh[0], eh[1]), pk2h(eh[2], eh[3]));
    }
    {   // K (unscaled), fp16 single
        float4 a = *(const float4*)(K + gb);
        float4 b = *(const float4*)(K + gb + 36);
        float rl[4] = { a.x * cl.x - b.x * sl.x, a.y * cl.y - b.y * sl.y,
                        a.z * cl.z - b.z * sl.z, a.w * cl.w - b.w * sl.w };
        float rh[4] = { b.x * ch.x + a.x * sh.x, b.y * ch.y + a.y * sh.y,
                        b.z * ch.z + a.z * sh.z, b.w * ch.w + a.w * sh.w };
        *(uint2*)(k16 + gb)      = make_uint2(pk2h(rl[0], rl[1]), pk2h(rl[2], rl[3]));
        *(uint2*)(k16 + gb + 36) = make_uint2(pk2h(rh[0], rh[1]), pk2h(rh[2], rh[3]));
    }
}

// ---------------------------------------------------------------------------
// HMMA flash attention: S = (Qhi+Qlo)·K fp16 2-term, PV fp16 1-term.
// ---------------------------------------------------------------------------
__global__ __launch_bounds__(256, 2) void attn_mma_kernel(
    const __half* __restrict__ QH, const __half* __restrict__ QL,
    const __half* __restrict__ K16g, const __half* __restrict__ V16g,
    __half* __restrict__ O16,
    const int* __restrict__ cu, int nseg)
{
    extern __shared__ __align__(16) char asmem[];
    const uint32_t sb = smem_u32(asmem);

    const int tid  = threadIdx.x;
    const int lane = tid & 31;
    const int w    = tid >> 5;
    const int h    = blockIdx.y;
    const int q0   = blockIdx.x * 128;

    int segStart = 0, segEnd = S_TOK;
    for (int i = 0; i < nseg; i++) {
        int a = cu[i], b = cu[i + 1];
        if (q0 >= a && q0 < b) { segStart = a; segEnd = b; }
    }
    const int ntiles = (segEnd - segStart + 31) / 32;

    // zero pad bytes (dims 72..79): Q rows + all 3 KV stage buffers (K, V)
    for (int i = tid; i < 128; i += 256) {
        *(uint4*)(asmem + AQ_H + i * A_ROWB + 144) = make_uint4(0, 0, 0, 0);
        *(uint4*)(asmem + AQ_L + i * A_ROWB + 144) = make_uint4(0, 0, 0, 0);
    }
    for (int i = tid; i < 3 * 32; i += 256) {
        const int b = i / 32, r = i % 32;
        char* rowp = asmem + AKV0 + b * KVS + r * A_ROWB + 144;
        *(uint4*)(rowp + KO) = make_uint4(0, 0, 0, 0);
        *(uint4*)(rowp + VO) = make_uint4(0, 0, 0, 0);
    }

    for (int i = tid; i < 128 * 9; i += 256) {
        const int r = i / 9, c = i % 9;
        const size_t g = (size_t)(q0 + r) * EMB + h * HD + c * 8;
        CP_ASYNC16(sb + AQ_H + r * A_ROWB + c * 16, QH + g);
        CP_ASYNC16(sb + AQ_L + r * A_ROWB + c * 16, QL + g);
    }
    CP_COMMIT();

    auto stage_kv = [&](int tt) {
        const int b = tt % 3;
        const int kt = segStart + tt * 32;
        const uint32_t dst0 = sb + AKV0 + b * KVS;
        for (int i = tid; i < 32 * 9; i += 256) {
            const int r = i / 9, c = i % 9;
            const int key = kt + r;
            if (key < segEnd) {
                const size_t g = (size_t)key * EMB + h * HD + c * 8;
                const uint32_t d = dst0 + r * A_ROWB + c * 16;
                CP_ASYNC16(d + KO, K16g + g);
                CP_ASYNC16(d + VO, V16g + g);
            }
        }
    };

    stage_kv(0); CP_COMMIT();
    if (ntiles > 1) { stage_kv(1); CP_COMMIT(); }

    const int j  = lane >> 3;
    const int l8 = lane & 7;
    const uint32_t q_off  = (uint32_t)((16 * w + (j & 1) * 8 + l8) * A_ROWB + (j >> 1) * 16);
    const uint32_t bs_off = (uint32_t)(((j >> 1) * 8 + l8) * A_ROWB + (j & 1) * 16);
    const uint32_t v_off  = (uint32_t)(((j & 1) * 8 + l8) * A_ROWB + (j >> 1) * 16);

    const int qr = lane >> 2;
    const int lc = lane & 3;

    float acc_o[10][4];
#pragma unroll
    for (int dt = 0; dt < 10; dt++)
#pragma unroll
        for (int e = 0; e < 4; e++) acc_o[dt][e] = 0.f;
    float lsum0 = 0.f, lsum1 = 0.f;

    for (int tt = 0; tt < ntiles; tt++) {
        const int kt = segStart + tt * 32;
        if (tt + 1 < ntiles) { CP_WAIT(1); } else { CP_WAIT(0); }
        __syncthreads();
        if (tt + 2 < ntiles) { stage_kv(tt + 2); CP_COMMIT(); }

        const uint32_t kvb = sb + AKV0 + (tt % 3) * KVS;

        if (kt + 32 > segEnd) {
            for (int i = tid; i < 32 * 9; i += 256) {
                const int r = i / 9, c = i % 9;
                if (kt + r >= segEnd) {
                    char* dp2 = asmem + (kvb - sb) + r * A_ROWB + c * 16;
                    *(uint4*)(dp2 + KO) = make_uint4(0, 0, 0, 0);
                    *(uint4*)(dp2 + VO) = make_uint4(0, 0, 0, 0);
                }
            }
            __syncthreads();
        }

        // ---- S = Q K^T (fp16 2-term: Qhi*K + Qlo*K), 32 keys --------------
        float acc_s[4][4];
#pragma unroll
        for (int nt = 0; nt < 4; nt++)
#pragma unroll
            for (int e = 0; e < 4; e++) acc_s[nt][e] = 0.f;

#pragma unroll
        for (int kc = 0; kc < 5; kc++) {
            uint32_t qh[4], ql[4];
            const uint32_t ao = sb + AQ_H + q_off + kc * 32;
            LDSM_X4(qh, ao);
            LDSM_X4(ql, ao + (AQ_L - AQ_H));
#pragma unroll
            for (int np = 0; np < 2; np++) {
                uint32_t bh[4];
                const uint32_t bo = kvb + KO + bs_off + np * (16 * A_ROWB) + kc * 32;
                LDSM_X4(bh, bo);
                MMA16816H(acc_s[2 * np],     qh, bh[0], bh[1]);
                MMA16816H(acc_s[2 * np],     ql, bh[0], bh[1]);
                MMA16816H(acc_s[2 * np + 1], qh, bh[2], bh[3]);
                MMA16816H(acc_s[2 * np + 1], ql, bh[2], bh[3]);
            }
        }

        // ---- softmax (unnormalized) + mask --------------------------------
#pragma unroll
        for (int nt = 0; nt < 4; nt++) {
            const int colb = kt + nt * 8 + lc * 2;
            float p0 = (colb     < segEnd) ? __expf(acc_s[nt][0]) : 0.f;
            float p1 = (colb + 1 < segEnd) ? __expf(acc_s[nt][1]) : 0.f;
            float p2 = (colb     < segEnd) ? __expf(acc_s[nt][2]) : 0.f;
            float p3 = (colb + 1 < segEnd) ? __expf(acc_s[nt][3]) : 0.f;
            lsum0 += p0 + p1;
            lsum1 += p2 + p3;
            acc_s[nt][0] = p0; acc_s[nt][1] = p1;
            acc_s[nt][2] = p2; acc_s[nt][3] = p3;
        }

        // ---- O += P V (fp16 1-term) ---------------------------------------
#pragma unroll
        for (int kc = 0; kc < 2; kc++) {
            uint32_t pa[4];
            const float* s0 = acc_s[2 * kc];
            const float* s1 = acc_s[2 * kc + 1];
            pa[0] = pk2h(s0[0], s0[1]); pa[1] = pk2h(s0[2], s0[3]);
            pa[2] = pk2h(s1[0], s1[1]); pa[3] = pk2h(s1[2], s1[3]);
#pragma unroll
            for (int dp = 0; dp < 5; dp++) {
                uint32_t vh[4];
                const uint32_t vo = kvb + VO + v_off + kc * (16 * A_ROWB) + dp * 32;
                LDSM_X4_T(vh, vo);
                MMA16816H(acc_o[2 * dp],     pa, vh[0], vh[1]);
                MMA16816H(acc_o[2 * dp + 1], pa, vh[2], vh[3]);
            }
        }
    }

    // ---- epilogue: normalize, write fp16 ----------------------------------
    lsum0 += __shfl_xor_sync(0xffffffffu, lsum0, 1);
    lsum0 += __shfl_xor_sync(0xffffffffu, lsum0, 2);
    lsum1 += __shfl_xor_sync(0xffffffffu, lsum1, 1);
    lsum1 += __shfl_xor_sync(0xffffffffu, lsum1, 2);
    const float inv0 = 1.0f / lsum0;
    const float inv1 = 1.0f / lsum1;
    const int row0 = q0 + 16 * w + qr;
    const int row1 = row0 + 8;
#pragma unroll
    for (int dt = 0; dt < 9; dt++) {
        const int d = dt * 8 + lc * 2;
        *(uint32_t*)(O16 + (size_t)row0 * EMB + h * HD + d) =
            pk2h(acc_o[dt][0] * inv0, acc_o[dt][1] * inv0);
        *(uint32_t*)(O16 + (size_t)row1 * EMB + h * HD + d) =
            pk2h(acc_o[dt][2] * inv1, acc_o[dt][3] * inv1);
    }
}

// ---------------------------------------------------------------------------
extern "C" void kernel_launch(void* const* d_in, const int* in_sizes, int n_in,
                              void* d_out, int out_size)
{
    const float* hs   = (const float*)d_in[0];
    const float* qw   = (const float*)d_in[1];
    const float* qb   = (const float*)d_in[2];
    const float* kw   = (const float*)d_in[3];
    const float* kb   = (const float*)d_in[4];
    const float* vw   = (const float*)d_in[5];
    const float* vb   = (const float*)d_in[6];
    const float* ow   = (const float*)d_in[7];
    const float* ob   = (const float*)d_in[8];
    const float* cosp = (const float*)d_in[9];
    const float* sinp = (const float*)d_in[10];
    const int*   cu   = (const int*)d_in[11];
    const int nseg = in_sizes[11] - 1;

    float *qp, *kp;
    __half *qh, *ql, *k16, *v16, *hs16, *a16, *w16;
    cudaGetSymbolAddress((void**)&qp, g_q);
    cudaGetSymbolAddress((void**)&kp, g_k);
    cudaGetSymbolAddress((void**)&qh, g_q_hi);
    cudaGetSymbolAddress((void**)&ql, g_q_lo);
    cudaGetSymbolAddress((void**)&k16, g_k_16);
    cudaGetSymbolAddress((void**)&v16, g_v_16);
    cudaGetSymbolAddress((void**)&hs16, g_hs16);
    cudaGetSymbolAddress((void**)&a16, g_a16);
    cudaGetSymbolAddress((void**)&w16, g_w16);

    cudaFuncSetAttribute(qkv_f16_kernel,
                         cudaFuncAttributeMaxDynamicSharedMemorySize, PRJ_SMEM);
    cudaFuncSetAttribute(oproj_f16_kernel,
                         cudaFuncAttributeMaxDynamicSharedMemorySize, PRJ_SMEM);
    cudaFuncSetAttribute(attn_mma_kernel,
                         cudaFuncAttributeMaxDynamicSharedMemorySize, ATTN_SMEM);

    // 0) conversions: hs + 4 weights -> fp16
    cvt_all_kernel<<<(CVT_TOTAL + 255) / 256, 256>>>(
        hs, qw, kw, vw, ow, hs16, w16);

    // 1) Q/K/V projections (fp16 1-term, one launch)
    qkv_f16_kernel<<<dim3(EMB / 64, S_TOK / 128, 3), 256, PRJ_SMEM>>>(
        hs16, w16, qb, kb, vb, qp, kp, v16);

    // 2) prep: RoPE + scale -> Q fp16 hi/lo, K fp16
    prep_qk_kernel<<<(S_TOK * NH * 9 + 255) / 256, 256>>>(
        qp, kp, qh, ql, k16, cosp, sinp);

    // 3) attention (S fp16 2-term, PV fp16 1-term) -> a16
    attn_mma_kernel<<<dim3(S_TOK / 128, NH), 256, ATTN_SMEM>>>(
        qh, ql, k16, v16, a16, cu, nseg);

    // 4) O projection (fp16 1-term) -> d_out
    oproj_f16_kernel<<<dim3(EMB / 64, S_TOK / 128), 256, PRJ_SMEM>>>(
        a16, w16 + 3 * (size_t)EMB * EMB, ob, (float*)d_out);
}